// round 1
// baseline (speedup 1.0000x reference)
#include <cuda_runtime.h>
#include <math.h>

// Problem constants
#define BB   16
#define TD   64
#define TE   64
#define HD   512
#define G3   1536
#define VV   32000
#define LOGITS_ELEMS (BB*TD*VV)   // 32768000

// ---------------- scratch (__device__ globals, no allocation) ----------------
__device__ float g_xp   [BB*TD*G3];       // x @ W_ih^T + b_ih
__device__ float g_part [2*16*BB*G3];     // double-buffered K-split partials of h @ W_hh^T
__device__ float g_dec  [BB*TD*HD];       // GRU outputs (masked)
__device__ float g_encp [BB*TE*HD];
__device__ float g_decp [BB*TD*HD];
__device__ float g_ctx  [BB*TD*HD];
__device__ float g_dense[BB*TD*HD];
__device__ float g_hlast[BB*HD];

__device__ unsigned int g_bar_cnt = 0;
__device__ unsigned int g_bar_gen = 0;

// ---------------- grid barrier (all blocks resident: 96 <= #SM) ----------------
__device__ __forceinline__ void grid_barrier(unsigned int nblocks) {
    __syncthreads();
    if (threadIdx.x == 0) {
        __threadfence();
        unsigned int gen = atomicAdd(&g_bar_gen, 0u);   // atomic load
        __threadfence();
        unsigned int ticket = atomicAdd(&g_bar_cnt, 1u);
        if (ticket == nblocks - 1u) {
            atomicExch(&g_bar_cnt, 0u);
            __threadfence();
            atomicAdd(&g_bar_gen, 1u);
        } else {
            while (atomicAdd(&g_bar_gen, 0u) == gen) { }
        }
        __threadfence();
    }
    __syncthreads();
}

// ---------------- generic NT SGEMM: C[m,n] = sum_k A[m,k]*B[n,k] (+C)(+bias)(tanh) ----------------
// M,N multiples of 64; K multiple of 16. 256 threads, 64x64 tile, 4x4 per thread.
#define FLAG_ACC  1
#define FLAG_TANH 2
__global__ void sgemm_nt(const float* __restrict__ A, int lda,
                         const float* __restrict__ B, int ldb,
                         const float* __restrict__ bias,
                         float* __restrict__ C, int ldc,
                         int K, int flags)
{
    __shared__ float As[16][64];
    __shared__ float Bs[16][64];
    const int bm = blockIdx.y * 64;
    const int bn = blockIdx.x * 64;
    const int tid = threadIdx.x;
    const int tr = tid >> 4;         // 0..15
    const int tc = tid & 15;         // 0..15
    const int lrow = tid >> 2;       // 0..63
    const int lcol = (tid & 3) * 4;  // 0,4,8,12

    float acc[4][4];
    #pragma unroll
    for (int i = 0; i < 4; i++)
        #pragma unroll
        for (int j = 0; j < 4; j++) acc[i][j] = 0.f;

    for (int k0 = 0; k0 < K; k0 += 16) {
        float4 av = *(const float4*)(A + (size_t)(bm + lrow) * lda + k0 + lcol);
        float4 bv = *(const float4*)(B + (size_t)(bn + lrow) * ldb + k0 + lcol);
        As[lcol + 0][lrow] = av.x; As[lcol + 1][lrow] = av.y;
        As[lcol + 2][lrow] = av.z; As[lcol + 3][lrow] = av.w;
        Bs[lcol + 0][lrow] = bv.x; Bs[lcol + 1][lrow] = bv.y;
        Bs[lcol + 2][lrow] = bv.z; Bs[lcol + 3][lrow] = bv.w;
        __syncthreads();
        #pragma unroll
        for (int kk = 0; kk < 16; kk++) {
            float a0 = As[kk][tr * 4 + 0], a1 = As[kk][tr * 4 + 1];
            float a2 = As[kk][tr * 4 + 2], a3 = As[kk][tr * 4 + 3];
            float b0 = Bs[kk][tc * 4 + 0], b1 = Bs[kk][tc * 4 + 1];
            float b2 = Bs[kk][tc * 4 + 2], b3 = Bs[kk][tc * 4 + 3];
            acc[0][0] += a0 * b0; acc[0][1] += a0 * b1; acc[0][2] += a0 * b2; acc[0][3] += a0 * b3;
            acc[1][0] += a1 * b0; acc[1][1] += a1 * b1; acc[1][2] += a1 * b2; acc[1][3] += a1 * b3;
            acc[2][0] += a2 * b0; acc[2][1] += a2 * b1; acc[2][2] += a2 * b2; acc[2][3] += a2 * b3;
            acc[3][0] += a3 * b0; acc[3][1] += a3 * b1; acc[3][2] += a3 * b2; acc[3][3] += a3 * b3;
        }
        __syncthreads();
    }

    #pragma unroll
    for (int i = 0; i < 4; i++) {
        int m = bm + tr * 4 + i;
        #pragma unroll
        for (int j = 0; j < 4; j++) {
            int n = bn + tc * 4 + j;
            float v = acc[i][j];
            if (flags & FLAG_ACC) v += C[(size_t)m * ldc + n];
            if (bias) v += bias[n];
            if (flags & FLAG_TANH) v = tanhf(v);
            C[(size_t)m * ldc + n] = v;
        }
    }
}

// ---------------- persistent GRU scan ----------------
// 96 blocks = 6 g-chunks (256 g) x 16 k-slices (32 h). W_hh slice pinned in SMEM.
// Per step: partial matmul -> grid barrier -> each block computes gates for
// exactly the h-slice it needs next step (h kept in SMEM). One barrier/step.
__global__ void gru_scan(const float* __restrict__ W_hh,
                         const float* __restrict__ b_hh,
                         const int*   __restrict__ lengths)
{
    __shared__ float sW[32 * 256];   // [hrel][g_local]
    __shared__ float sh[32 * 16];    // [hrel][b] current hidden slice

    const int tid    = threadIdx.x;
    const int gchunk = blockIdx.x / 16;
    const int ks     = blockIdx.x % 16;
    const int g0     = gchunk * 256;
    const int hs0    = ks * 32;
    const int gg     = g0 + tid;

    // load W_hh[gg, hs0..hs0+32) once (kept all 64 steps)
    {
        const float4* wr = (const float4*)(W_hh + (size_t)gg * HD + hs0);
        #pragma unroll
        for (int q = 0; q < 8; q++) {
            float4 v = wr[q];
            sW[(q * 4 + 0) * 256 + tid] = v.x;
            sW[(q * 4 + 1) * 256 + tid] = v.y;
            sW[(q * 4 + 2) * 256 + tid] = v.z;
            sW[(q * 4 + 3) * 256 + tid] = v.w;
        }
    }
    sh[tid] = 0.f;
    sh[tid + 256] = 0.f;
    __syncthreads();

    const int len0 = lengths[(tid >> 5) & 15];  // not used; per-p load below
    (void)len0;

    for (int t = 0; t < TD; t++) {
        const int buf = t & 1;

        // ---- partial matmul: acc[b] = sum_{hrel} W[hrel][tid] * h[hrel][b]
        float acc[16];
        #pragma unroll
        for (int b = 0; b < 16; b++) acc[b] = 0.f;
        #pragma unroll
        for (int hrel = 0; hrel < 32; hrel++) {
            float w = sW[hrel * 256 + tid];
            const float4* hv = (const float4*)(sh + hrel * 16);
            float4 h0 = hv[0], h1 = hv[1], h2 = hv[2], h3 = hv[3];
            acc[0]  += w * h0.x; acc[1]  += w * h0.y; acc[2]  += w * h0.z; acc[3]  += w * h0.w;
            acc[4]  += w * h1.x; acc[5]  += w * h1.y; acc[6]  += w * h1.z; acc[7]  += w * h1.w;
            acc[8]  += w * h2.x; acc[9]  += w * h2.y; acc[10] += w * h2.z; acc[11] += w * h2.w;
            acc[12] += w * h3.x; acc[13] += w * h3.y; acc[14] += w * h3.z; acc[15] += w * h3.w;
        }
        {
            float* pbase = g_part + (size_t)(buf * 16 + ks) * (BB * G3);
            #pragma unroll
            for (int b = 0; b < 16; b++) pbase[(size_t)b * G3 + gg] = acc[b];
        }

        grid_barrier(96);

        // ---- gates for j in [hs0, hs0+32), all b — exactly the h this block needs
        #pragma unroll
        for (int i = 0; i < 2; i++) {
            int p    = tid + i * 256;
            int b    = p >> 5;
            int jrel = p & 31;
            int j    = hs0 + jrel;
            float rs = 0.f, zs = 0.f, ns = 0.f;
            const float* pb = g_part + (size_t)buf * 16 * BB * G3 + (size_t)b * G3;
            #pragma unroll
            for (int k2 = 0; k2 < 16; k2++) {
                const float* pp = pb + (size_t)k2 * (BB * G3);
                rs += pp[j];
                zs += pp[512 + j];
                ns += pp[1024 + j];
            }
            rs += b_hh[j];
            zs += b_hh[512 + j];
            ns += b_hh[1024 + j];
            const float* xr = g_xp + ((size_t)b * TD + t) * G3;
            float r = 1.f / (1.f + expf(-(xr[j] + rs)));
            float z = 1.f / (1.f + expf(-(xr[512 + j] + zs)));
            float n = tanhf(xr[1024 + j] + r * ns);
            float hold = sh[jrel * 16 + b];
            float hnew = (1.f - z) * n + z * hold;
            bool  valid = (t < lengths[b]);
            float hkeep = valid ? hnew : hold;
            sh[jrel * 16 + b] = hkeep;
            if (gchunk == 0) {
                g_dec[((size_t)b * TD + t) * HD + j] = valid ? hnew : 0.f;
                if (t == TD - 1) g_hlast[(size_t)b * HD + j] = hkeep;
            }
        }
        __syncthreads();
    }
}

// ---------------- attention: per (b,d) block ----------------
// masked-softmax simplification: softmax over unmasked e only (mask terms cancel)
__global__ void attn_kernel(const float* __restrict__ encp,
                            const float* __restrict__ decp,
                            const float* __restrict__ enc,
                            const int*   __restrict__ dlen,
                            const int*   __restrict__ elen,
                            const float* __restrict__ b_attn,
                            const float* __restrict__ v_w,
                            float* __restrict__ context)
{
    const int bd = blockIdx.x;
    const int b  = bd >> 6;
    const int d  = bd & 63;
    const int tid = threadIdx.x;

    __shared__ float s_dp[HD];
    __shared__ float s_vw[HD];
    __shared__ float s_en[TE];
    __shared__ float s_mx, s_ssum;

    float* ctx_out = context + (size_t)bd * HD;
    const int Dl = dlen[b];
    const int El = elen[b];

    if (d >= Dl) {
        for (int i = tid; i < HD; i += 256) ctx_out[i] = 0.f;
        return;
    }

    for (int i = tid; i < HD; i += 256) {
        s_dp[i] = decp[(size_t)bd * HD + i] + b_attn[i];
        s_vw[i] = v_w[i];
    }
    __syncthreads();

    const int warp = tid >> 5, lane = tid & 31;
    for (int e = warp; e < El; e += 8) {
        const float* ep = encp + ((size_t)b * TE + e) * HD;
        float sum = 0.f;
        #pragma unroll 4
        for (int h = lane; h < HD; h += 32)
            sum += tanhf(ep[h] + s_dp[h]) * s_vw[h];
        #pragma unroll
        for (int off = 16; off; off >>= 1)
            sum += __shfl_xor_sync(0xffffffffu, sum, off);
        if (lane == 0) s_en[e] = sum;
    }
    __syncthreads();

    if (tid < 32) {
        float mx = -1e30f;
        for (int e = lane; e < El; e += 32) mx = fmaxf(mx, s_en[e]);
        #pragma unroll
        for (int off = 16; off; off >>= 1)
            mx = fmaxf(mx, __shfl_xor_sync(0xffffffffu, mx, off));
        float ss = 0.f;
        for (int e = lane; e < El; e += 32) ss += expf(s_en[e] - mx);
        #pragma unroll
        for (int off = 16; off; off >>= 1)
            ss += __shfl_xor_sync(0xffffffffu, ss, off);
        if (lane == 0) { s_mx = mx; s_ssum = ss; }
    }
    __syncthreads();
    if (tid < TE) s_en[tid] = (tid < El) ? expf(s_en[tid] - s_mx) / s_ssum : 0.f;
    __syncthreads();

    for (int h = tid; h < HD; h += 256) {
        float a = 0.f;
        for (int e = 0; e < El; e++)
            a += s_en[e] * enc[((size_t)b * TE + e) * HD + h];
        ctx_out[h] = a;
    }
}

__global__ void copy_hlast(float* __restrict__ out)
{
    out[blockIdx.x * HD + threadIdx.x] = g_hlast[blockIdx.x * HD + threadIdx.x];
}

// ---------------- launch ----------------
extern "C" void kernel_launch(void* const* d_in, const int* in_sizes, int n_in,
                              void* d_out, int out_size)
{
    const float* x      = (const float*)d_in[0];   // (16,64,512)
    const int*   inlen  = (const int*)  d_in[1];   // (16,)
    const float* enc    = (const float*)d_in[2];   // (16,64,512)
    const int*   enclen = (const int*)  d_in[3];   // (16,)
    const float* W_ih   = (const float*)d_in[4];   // (1536,512)
    const float* W_hh   = (const float*)d_in[5];   // (1536,512)
    const float* b_ih   = (const float*)d_in[6];
    const float* b_hh   = (const float*)d_in[7];
    const float* W_attn = (const float*)d_in[8];   // (512,1024)
    const float* b_attn = (const float*)d_in[9];
    const float* v_w    = (const float*)d_in[10];
    // d_in[11] = v_b : softmax-invariant constant shift, cancels exactly
    const float* W_dense= (const float*)d_in[12];  // (512,1024)
    const float* b_dense= (const float*)d_in[13];
    const float* W_out  = (const float*)d_in[14];  // (32000,512)
    const float* b_out  = (const float*)d_in[15];

    float* out = (float*)d_out;

    float* xp    = nullptr; cudaGetSymbolAddress((void**)&xp,    g_xp);
    float* dec   = nullptr; cudaGetSymbolAddress((void**)&dec,   g_dec);
    float* encp  = nullptr; cudaGetSymbolAddress((void**)&encp,  g_encp);
    float* decp  = nullptr; cudaGetSymbolAddress((void**)&decp,  g_decp);
    float* ctx   = nullptr; cudaGetSymbolAddress((void**)&ctx,   g_ctx);
    float* dense = nullptr; cudaGetSymbolAddress((void**)&dense, g_dense);

    // 1) x_proj = x @ W_ih^T + b_ih        (1024 x 1536 x 512)
    sgemm_nt<<<dim3(G3 / 64, (BB * TD) / 64), 256>>>(x, HD, W_ih, HD, b_ih, xp, G3, HD, 0);

    // 2) GRU scan (persistent, 64 steps)
    gru_scan<<<96, 256>>>(W_hh, b_hh, inlen);

    // 3) enc_p = enc @ We^T ; 4) dec_p = dec @ Wd^T   (1024 x 512 x 512 each)
    sgemm_nt<<<dim3(HD / 64, (BB * TE) / 64), 256>>>(enc, HD, W_attn,      2 * HD, nullptr, encp, HD, HD, 0);
    sgemm_nt<<<dim3(HD / 64, (BB * TD) / 64), 256>>>(dec, HD, W_attn + HD, 2 * HD, nullptr, decp, HD, HD, 0);

    // 5) attention -> context
    attn_kernel<<<BB * TD, 256>>>(encp, decp, enc, inlen, enclen, b_attn, v_w, ctx);

    // 6,7) dense = tanh([dec,ctx] @ W_dense^T + b_dense)
    sgemm_nt<<<dim3(HD / 64, (BB * TD) / 64), 256>>>(dec, HD, W_dense,      2 * HD, nullptr, dense, HD, HD, 0);
    sgemm_nt<<<dim3(HD / 64, (BB * TD) / 64), 256>>>(ctx, HD, W_dense + HD, 2 * HD, b_dense, dense, HD, HD, FLAG_ACC | FLAG_TANH);

    // 8) logits = dense @ W_out^T + b_out   (1024 x 32000 x 512) -> d_out
    sgemm_nt<<<dim3(VV / 64, (BB * TD) / 64), 256>>>(dense, HD, W_out, HD, b_out, out, VV, HD, 0);

    // 9) h_last -> tail of d_out
    copy_hlast<<<BB, HD>>>(out + LOGITS_ELEMS);
}

// round 7
// speedup vs baseline: 1.4421x; 1.4421x over previous
#include <cuda_runtime.h>
#include <cuda_bf16.h>
#include <mma.h>
#include <math.h>
#include <stdint.h>

using namespace nvcuda;

// Problem constants
#define BB   16
#define TD   64
#define TE   64
#define HD   512
#define G3   1536
#define VV   32000
#define LOGITS_ELEMS (BB*TD*VV)   // 32768000

// ---------------- scratch (__device__ globals, no allocation) ----------------
__device__ float g_xp   [BB*TD*G3];
__device__ float g_part [2*16*BB*G3];
__device__ float g_dec  [BB*TD*HD];
__device__ float g_encp [BB*TE*HD];
__device__ float g_decp [BB*TD*HD];
__device__ float g_ctx  [BB*TD*HD];
__device__ float g_dense[BB*TD*HD];
__device__ float g_hlast[BB*HD];

// bf16 hi/lo split operands for the tensor-core logits GEMM
__device__ __nv_bfloat16 g_Ahi[BB*TD*HD];
__device__ __nv_bfloat16 g_Alo[BB*TD*HD];
__device__ __nv_bfloat16 g_Bhi[(size_t)VV*HD];
__device__ __nv_bfloat16 g_Blo[(size_t)VV*HD];

__device__ unsigned int g_bar_cnt = 0;
__device__ unsigned int g_bar_gen = 0;

// ---------------- helpers (baseline-PTX only) ----------------
__device__ __forceinline__ uint32_t smem_u32(const void* p) {
    uint32_t a;
    asm("{ .reg .u64 t; cvta.to.shared.u64 t, %1; cvt.u32.u64 %0, t; }" : "=r"(a) : "l"(p));
    return a;
}
__device__ __forceinline__ void cp16(uint32_t s, const void* g) {
    asm volatile("cp.async.cg.shared.global [%0], [%1], 16;" :: "r"(s), "l"(g));
}

// ---------------- grid barrier ----------------
__device__ __forceinline__ void grid_barrier(unsigned int nblocks) {
    __syncthreads();
    if (threadIdx.x == 0) {
        __threadfence();
        unsigned int gen = atomicAdd(&g_bar_gen, 0u);
        __threadfence();
        unsigned int ticket = atomicAdd(&g_bar_cnt, 1u);
        if (ticket == nblocks - 1u) {
            atomicExch(&g_bar_cnt, 0u);
            __threadfence();
            atomicAdd(&g_bar_gen, 1u);
        } else {
            while (atomicAdd(&g_bar_gen, 0u) == gen) { }
        }
        __threadfence();
    }
    __syncthreads();
}

// ---------------- generic NT SGEMM (small GEMMs only) ----------------
#define FLAG_ACC  1
#define FLAG_TANH 2
__global__ void sgemm_nt(const float* __restrict__ A, int lda,
                         const float* __restrict__ B, int ldb,
                         const float* __restrict__ bias,
                         float* __restrict__ C, int ldc,
                         int K, int flags)
{
    __shared__ float As[16][64];
    __shared__ float Bs[16][64];
    const int bm = blockIdx.y * 64;
    const int bn = blockIdx.x * 64;
    const int tid = threadIdx.x;
    const int tr = tid >> 4;
    const int tc = tid & 15;
    const int lrow = tid >> 2;
    const int lcol = (tid & 3) * 4;

    float acc[4][4];
    #pragma unroll
    for (int i = 0; i < 4; i++)
        #pragma unroll
        for (int j = 0; j < 4; j++) acc[i][j] = 0.f;

    for (int k0 = 0; k0 < K; k0 += 16) {
        float4 av = *(const float4*)(A + (size_t)(bm + lrow) * lda + k0 + lcol);
        float4 bv = *(const float4*)(B + (size_t)(bn + lrow) * ldb + k0 + lcol);
        As[lcol + 0][lrow] = av.x; As[lcol + 1][lrow] = av.y;
        As[lcol + 2][lrow] = av.z; As[lcol + 3][lrow] = av.w;
        Bs[lcol + 0][lrow] = bv.x; Bs[lcol + 1][lrow] = bv.y;
        Bs[lcol + 2][lrow] = bv.z; Bs[lcol + 3][lrow] = bv.w;
        __syncthreads();
        #pragma unroll
        for (int kk = 0; kk < 16; kk++) {
            float a0 = As[kk][tr * 4 + 0], a1 = As[kk][tr * 4 + 1];
            float a2 = As[kk][tr * 4 + 2], a3 = As[kk][tr * 4 + 3];
            float b0 = Bs[kk][tc * 4 + 0], b1 = Bs[kk][tc * 4 + 1];
            float b2 = Bs[kk][tc * 4 + 2], b3 = Bs[kk][tc * 4 + 3];
            acc[0][0] += a0 * b0; acc[0][1] += a0 * b1; acc[0][2] += a0 * b2; acc[0][3] += a0 * b3;
            acc[1][0] += a1 * b0; acc[1][1] += a1 * b1; acc[1][2] += a1 * b2; acc[1][3] += a1 * b3;
            acc[2][0] += a2 * b0; acc[2][1] += a2 * b1; acc[2][2] += a2 * b2; acc[2][3] += a2 * b3;
            acc[3][0] += a3 * b0; acc[3][1] += a3 * b1; acc[3][2] += a3 * b2; acc[3][3] += a3 * b3;
        }
        __syncthreads();
    }

    #pragma unroll
    for (int i = 0; i < 4; i++) {
        int m = bm + tr * 4 + i;
        #pragma unroll
        for (int j = 0; j < 4; j++) {
            int n = bn + tc * 4 + j;
            float v = acc[i][j];
            if (flags & FLAG_ACC) v += C[(size_t)m * ldc + n];
            if (bias) v += bias[n];
            if (flags & FLAG_TANH) v = tanhf(v);
            C[(size_t)m * ldc + n] = v;
        }
    }
}

// ---------------- persistent GRU scan (unchanged, passing) ----------------
__global__ void gru_scan(const float* __restrict__ W_hh,
                         const float* __restrict__ b_hh,
                         const int*   __restrict__ lengths)
{
    __shared__ float sW[32 * 256];
    __shared__ float sh[32 * 16];

    const int tid    = threadIdx.x;
    const int gchunk = blockIdx.x / 16;
    const int ks     = blockIdx.x % 16;
    const int g0     = gchunk * 256;
    const int hs0    = ks * 32;
    const int gg     = g0 + tid;

    {
        const float4* wr = (const float4*)(W_hh + (size_t)gg * HD + hs0);
        #pragma unroll
        for (int q = 0; q < 8; q++) {
            float4 v = wr[q];
            sW[(q * 4 + 0) * 256 + tid] = v.x;
            sW[(q * 4 + 1) * 256 + tid] = v.y;
            sW[(q * 4 + 2) * 256 + tid] = v.z;
            sW[(q * 4 + 3) * 256 + tid] = v.w;
        }
    }
    sh[tid] = 0.f;
    sh[tid + 256] = 0.f;
    __syncthreads();

    for (int t = 0; t < TD; t++) {
        const int buf = t & 1;

        float acc[16];
        #pragma unroll
        for (int b = 0; b < 16; b++) acc[b] = 0.f;
        #pragma unroll
        for (int hrel = 0; hrel < 32; hrel++) {
            float w = sW[hrel * 256 + tid];
            const float4* hv = (const float4*)(sh + hrel * 16);
            float4 h0 = hv[0], h1 = hv[1], h2 = hv[2], h3 = hv[3];
            acc[0]  += w * h0.x; acc[1]  += w * h0.y; acc[2]  += w * h0.z; acc[3]  += w * h0.w;
            acc[4]  += w * h1.x; acc[5]  += w * h1.y; acc[6]  += w * h1.z; acc[7]  += w * h1.w;
            acc[8]  += w * h2.x; acc[9]  += w * h2.y; acc[10] += w * h2.z; acc[11] += w * h2.w;
            acc[12] += w * h3.x; acc[13] += w * h3.y; acc[14] += w * h3.z; acc[15] += w * h3.w;
        }
        {
            float* pbase = g_part + (size_t)(buf * 16 + ks) * (BB * G3);
            #pragma unroll
            for (int b = 0; b < 16; b++) pbase[(size_t)b * G3 + gg] = acc[b];
        }

        grid_barrier(96);

        #pragma unroll
        for (int i = 0; i < 2; i++) {
            int p    = tid + i * 256;
            int b    = p >> 5;
            int jrel = p & 31;
            int j    = hs0 + jrel;
            float rs = 0.f, zs = 0.f, ns = 0.f;
            const float* pb = g_part + (size_t)buf * 16 * BB * G3 + (size_t)b * G3;
            #pragma unroll
            for (int k2 = 0; k2 < 16; k2++) {
                const float* pp = pb + (size_t)k2 * (BB * G3);
                rs += pp[j];
                zs += pp[512 + j];
                ns += pp[1024 + j];
            }
            rs += b_hh[j];
            zs += b_hh[512 + j];
            ns += b_hh[1024 + j];
            const float* xr = g_xp + ((size_t)b * TD + t) * G3;
            float r = 1.f / (1.f + expf(-(xr[j] + rs)));
            float z = 1.f / (1.f + expf(-(xr[512 + j] + zs)));
            float n = tanhf(xr[1024 + j] + r * ns);
            float hold = sh[jrel * 16 + b];
            float hnew = (1.f - z) * n + z * hold;
            bool  valid = (t < lengths[b]);
            float hkeep = valid ? hnew : hold;
            sh[jrel * 16 + b] = hkeep;
            if (gchunk == 0) {
                g_dec[((size_t)b * TD + t) * HD + j] = valid ? hnew : 0.f;
                if (t == TD - 1) g_hlast[(size_t)b * HD + j] = hkeep;
            }
        }
        __syncthreads();
    }
}

// ---------------- attention (unchanged, passing) ----------------
__global__ void attn_kernel(const float* __restrict__ encp,
                            const float* __restrict__ decp,
                            const float* __restrict__ enc,
                            const int*   __restrict__ dlen,
                            const int*   __restrict__ elen,
                            const float* __restrict__ b_attn,
                            const float* __restrict__ v_w,
                            float* __restrict__ context)
{
    const int bd = blockIdx.x;
    const int b  = bd >> 6;
    const int d  = bd & 63;
    const int tid = threadIdx.x;

    __shared__ float s_dp[HD];
    __shared__ float s_vw[HD];
    __shared__ float s_en[TE];
    __shared__ float s_mx, s_ssum;

    float* ctx_out = context + (size_t)bd * HD;
    const int Dl = dlen[b];
    const int El = elen[b];

    if (d >= Dl) {
        for (int i = tid; i < HD; i += 256) ctx_out[i] = 0.f;
        return;
    }

    for (int i = tid; i < HD; i += 256) {
        s_dp[i] = decp[(size_t)bd * HD + i] + b_attn[i];
        s_vw[i] = v_w[i];
    }
    __syncthreads();

    const int warp = tid >> 5, lane = tid & 31;
    for (int e = warp; e < El; e += 8) {
        const float* ep = encp + ((size_t)b * TE + e) * HD;
        float sum = 0.f;
        #pragma unroll 4
        for (int h = lane; h < HD; h += 32)
            sum += tanhf(ep[h] + s_dp[h]) * s_vw[h];
        #pragma unroll
        for (int off = 16; off; off >>= 1)
            sum += __shfl_xor_sync(0xffffffffu, sum, off);
        if (lane == 0) s_en[e] = sum;
    }
    __syncthreads();

    if (tid < 32) {
        float mx = -1e30f;
        for (int e = lane; e < El; e += 32) mx = fmaxf(mx, s_en[e]);
        #pragma unroll
        for (int off = 16; off; off >>= 1)
            mx = fmaxf(mx, __shfl_xor_sync(0xffffffffu, mx, off));
        float ss = 0.f;
        for (int e = lane; e < El; e += 32) ss += expf(s_en[e] - mx);
        #pragma unroll
        for (int off = 16; off; off >>= 1)
            ss += __shfl_xor_sync(0xffffffffu, ss, off);
        if (lane == 0) { s_mx = mx; s_ssum = ss; }
    }
    __syncthreads();
    if (tid < TE) s_en[tid] = (tid < El) ? expf(s_en[tid] - s_mx) / s_ssum : 0.f;
    __syncthreads();

    for (int h = tid; h < HD; h += 256) {
        float a = 0.f;
        for (int e = 0; e < El; e++)
            a += s_en[e] * enc[((size_t)b * TE + e) * HD + h];
        ctx_out[h] = a;
    }
}

__global__ void copy_hlast(float* __restrict__ out)
{
    out[blockIdx.x * HD + threadIdx.x] = g_hlast[blockIdx.x * HD + threadIdx.x];
}

// ---------------- fp32 -> bf16 hi/lo split ----------------
__global__ void split_bf16(const float* __restrict__ src,
                           __nv_bfloat16* __restrict__ hi,
                           __nv_bfloat16* __restrict__ lo, int n)
{
    int i = (blockIdx.x * 256 + threadIdx.x) * 4;
    if (i >= n) return;
    float4 v = *(const float4*)(src + i);
    __nv_bfloat16 h0 = __float2bfloat16(v.x);
    __nv_bfloat16 h1 = __float2bfloat16(v.y);
    __nv_bfloat16 h2 = __float2bfloat16(v.z);
    __nv_bfloat16 h3 = __float2bfloat16(v.w);
    __nv_bfloat16 l0 = __float2bfloat16(v.x - __bfloat162float(h0));
    __nv_bfloat16 l1 = __float2bfloat16(v.y - __bfloat162float(h1));
    __nv_bfloat16 l2 = __float2bfloat16(v.z - __bfloat162float(h2));
    __nv_bfloat16 l3 = __float2bfloat16(v.w - __bfloat162float(h3));
    __nv_bfloat162* hp = (__nv_bfloat162*)(hi + i);
    __nv_bfloat162* lp = (__nv_bfloat162*)(lo + i);
    hp[0] = __nv_bfloat162(h0, h1); hp[1] = __nv_bfloat162(h2, h3);
    lp[0] = __nv_bfloat162(l0, l1); lp[1] = __nv_bfloat162(l2, l3);
}

// ---------------- wmma (HMMA) logits GEMM ----------------
// D[1024,32000] = Ahi*Bhi^T + Ahi*Blo^T + Alo*Bhi^T + bias, fp32 accum.
// CTA tile 128x128, K=512 in chunks of 32, cp.async double buffer.
// 8 warps: warp_m = wid>>2 (2), warp_n = wid&3 (4); warp tile 64x32 = 4x2 wmma frags.
#define LBK   32
#define LDT   40                          // LBK + 8 pad (bf16 elems); row = 80 B
#define ARR_ELEMS (128 * LDT)             // 5120 bf16 per array
#define STAGE_ELEMS (4 * ARR_ELEMS)       // Ahi|Alo|Bhi|Blo = 20480 bf16 = 40960 B
#define SMEM_LOGITS (2 * STAGE_ELEMS * 2) // 81920 B (also covers 128x132 f32 staging = 67584 B)
#define LDC_S 132

__device__ __forceinline__ void load_stage_logits(int tid, int mt, int nt, int c,
                                                  uint32_t smbase, int s)
{
    const __nv_bfloat16* srcs[4] = {
        g_Ahi + (size_t)mt * 128 * HD,
        g_Alo + (size_t)mt * 128 * HD,
        g_Bhi + (size_t)nt * 128 * HD,
        g_Blo + (size_t)nt * 128 * HD
    };
    #pragma unroll
    for (int arr = 0; arr < 4; arr++) {
        #pragma unroll
        for (int it = 0; it < 2; it++) {
            int i  = tid + it * 256;        // 0..511 : 128 rows x 4 float4s
            int r  = i >> 2;
            int c4 = i & 3;
            const void* src = srcs[arr] + (size_t)r * HD + c * LBK + c4 * 8;
            uint32_t dst = smbase + (uint32_t)(s * STAGE_ELEMS + arr * ARR_ELEMS) * 2u
                         + (uint32_t)(r * (LDT * 2) + c4 * 16);
            cp16(dst, src);
        }
    }
    asm volatile("cp.async.commit_group;" ::: "memory");
}

__global__ void __launch_bounds__(256, 1) logits_wmma(const float* __restrict__ b_out,
                                                      float* __restrict__ out)
{
    extern __shared__ __align__(16) char dynsmem[];
    __nv_bfloat16* sm = (__nv_bfloat16*)dynsmem;
    const uint32_t smbase = smem_u32(dynsmem);

    const int tid = threadIdx.x;
    const int wid = tid >> 5;
    const int nt = blockIdx.x;      // 0..249
    const int mt = blockIdx.y;      // 0..7
    const int warp_m = wid >> 2;    // 0..1
    const int warp_n = wid & 3;     // 0..3

    wmma::fragment<wmma::accumulator, 16, 16, 16, float> acc[4][2];
    #pragma unroll
    for (int i = 0; i < 4; i++)
        #pragma unroll
        for (int j = 0; j < 2; j++)
            wmma::fill_fragment(acc[i][j], 0.f);

    // prologue
    load_stage_logits(tid, mt, nt, 0, smbase, 0);
    load_stage_logits(tid, mt, nt, 1, smbase, 1);

    for (int c = 0; c < 16; c++) {
        const int s = c & 1;
        if (c < 15) asm volatile("cp.async.wait_group 1;" ::: "memory");
        else        asm volatile("cp.async.wait_group 0;" ::: "memory");
        __syncthreads();

        const __nv_bfloat16* As_hi = sm + s * STAGE_ELEMS;
        const __nv_bfloat16* As_lo = As_hi + ARR_ELEMS;
        const __nv_bfloat16* Bs_hi = As_lo + ARR_ELEMS;
        const __nv_bfloat16* Bs_lo = Bs_hi + ARR_ELEMS;

        #pragma unroll
        for (int kk = 0; kk < LBK; kk += 16) {
            wmma::fragment<wmma::matrix_a, 16, 16, 16, __nv_bfloat16, wmma::row_major> a_hi[4], a_lo[4];
            wmma::fragment<wmma::matrix_b, 16, 16, 16, __nv_bfloat16, wmma::col_major> b_hi[2], b_lo[2];
            #pragma unroll
            for (int i = 0; i < 4; i++) {
                int r0 = warp_m * 64 + i * 16;
                wmma::load_matrix_sync(a_hi[i], As_hi + r0 * LDT + kk, LDT);
                wmma::load_matrix_sync(a_lo[i], As_lo + r0 * LDT + kk, LDT);
            }
            #pragma unroll
            for (int j = 0; j < 2; j++) {
                int n0 = warp_n * 32 + j * 16;
                wmma::load_matrix_sync(b_hi[j], Bs_hi + n0 * LDT + kk, LDT);
                wmma::load_matrix_sync(b_lo[j], Bs_lo + n0 * LDT + kk, LDT);
            }
            #pragma unroll
            for (int i = 0; i < 4; i++)
                #pragma unroll
                for (int j = 0; j < 2; j++) {
                    wmma::mma_sync(acc[i][j], a_hi[i], b_hi[j], acc[i][j]);
                    wmma::mma_sync(acc[i][j], a_hi[i], b_lo[j], acc[i][j]);
                    wmma::mma_sync(acc[i][j], a_lo[i], b_hi[j], acc[i][j]);
                }
        }
        __syncthreads();

        if (c + 2 < 16) load_stage_logits(tid, mt, nt, c + 2, smbase, s);
    }

    // epilogue: stage fp32 result in smem, add bias, write out
    __syncthreads();
    float* cs = (float*)dynsmem;   // 128 x LDC_S
    #pragma unroll
    for (int i = 0; i < 4; i++)
        #pragma unroll
        for (int j = 0; j < 2; j++)
            wmma::store_matrix_sync(cs + (warp_m * 64 + i * 16) * LDC_S + (warp_n * 32 + j * 16),
                                    acc[i][j], LDC_S, wmma::mem_row_major);
    __syncthreads();

    const int n0 = nt * 128;
    #pragma unroll
    for (int it = 0; it < 16; it++) {
        int i  = tid + it * 256;      // 0..4095 : 128 rows x 32 float4s
        int r  = i >> 5;
        int c4 = (i & 31) * 4;
        float4 v = *(float4*)(cs + r * LDC_S + c4);
        v.x += b_out[n0 + c4 + 0];
        v.y += b_out[n0 + c4 + 1];
        v.z += b_out[n0 + c4 + 2];
        v.w += b_out[n0 + c4 + 3];
        *(float4*)(out + (size_t)(mt * 128 + r) * VV + n0 + c4) = v;
    }
}

// ---------------- launch ----------------
extern "C" void kernel_launch(void* const* d_in, const int* in_sizes, int n_in,
                              void* d_out, int out_size)
{
    const float* x      = (const float*)d_in[0];
    const int*   inlen  = (const int*)  d_in[1];
    const float* enc    = (const float*)d_in[2];
    const int*   enclen = (const int*)  d_in[3];
    const float* W_ih   = (const float*)d_in[4];
    const float* W_hh   = (const float*)d_in[5];
    const float* b_ih   = (const float*)d_in[6];
    const float* b_hh   = (const float*)d_in[7];
    const float* W_attn = (const float*)d_in[8];
    const float* b_attn = (const float*)d_in[9];
    const float* v_w    = (const float*)d_in[10];
    const float* W_dense= (const float*)d_in[12];
    const float* b_dense= (const float*)d_in[13];
    const float* W_out  = (const float*)d_in[14];
    const float* b_out  = (const float*)d_in[15];

    float* out = (float*)d_out;

    float* xp    = nullptr; cudaGetSymbolAddress((void**)&xp,    g_xp);
    float* dec   = nullptr; cudaGetSymbolAddress((void**)&dec,   g_dec);
    float* encp  = nullptr; cudaGetSymbolAddress((void**)&encp,  g_encp);
    float* decp  = nullptr; cudaGetSymbolAddress((void**)&decp,  g_decp);
    float* ctx   = nullptr; cudaGetSymbolAddress((void**)&ctx,   g_ctx);
    float* dense = nullptr; cudaGetSymbolAddress((void**)&dense, g_dense);
    __nv_bfloat16* Ahi = nullptr; cudaGetSymbolAddress((void**)&Ahi, g_Ahi);
    __nv_bfloat16* Alo = nullptr; cudaGetSymbolAddress((void**)&Alo, g_Alo);
    __nv_bfloat16* Bhi = nullptr; cudaGetSymbolAddress((void**)&Bhi, g_Bhi);
    __nv_bfloat16* Blo = nullptr; cudaGetSymbolAddress((void**)&Blo, g_Blo);

    cudaFuncSetAttribute(logits_wmma, cudaFuncAttributeMaxDynamicSharedMemorySize, SMEM_LOGITS);

    // 1) x_proj
    sgemm_nt<<<dim3(G3 / 64, (BB * TD) / 64), 256>>>(x, HD, W_ih, HD, b_ih, xp, G3, HD, 0);

    // W_out split (independent of everything upstream)
    split_bf16<<<((size_t)VV * HD) / 1024, 256>>>(W_out, Bhi, Blo, VV * HD);

    // 2) GRU scan
    gru_scan<<<96, 256>>>(W_hh, b_hh, inlen);

    // 3,4) attention projections
    sgemm_nt<<<dim3(HD / 64, (BB * TE) / 64), 256>>>(enc, HD, W_attn,      2 * HD, nullptr, encp, HD, HD, 0);
    sgemm_nt<<<dim3(HD / 64, (BB * TD) / 64), 256>>>(dec, HD, W_attn + HD, 2 * HD, nullptr, decp, HD, HD, 0);

    // 5) attention
    attn_kernel<<<BB * TD, 256>>>(encp, decp, enc, inlen, enclen, b_attn, v_w, ctx);

    // 6,7) dense
    sgemm_nt<<<dim3(HD / 64, (BB * TD) / 64), 256>>>(dec, HD, W_dense,      2 * HD, nullptr, dense, HD, HD, 0);
    sgemm_nt<<<dim3(HD / 64, (BB * TD) / 64), 256>>>(ctx, HD, W_dense + HD, 2 * HD, b_dense, dense, HD, HD, FLAG_ACC | FLAG_TANH);

    // 8) logits via wmma/HMMA (bf16 hi/lo split, fp32 accumulate)
    split_bf16<<<(BB * TD * HD) / 1024, 256>>>(dense, Ahi, Alo, BB * TD * HD);
    logits_wmma<<<dim3(VV / 128, (BB * TD) / 128), 256, SMEM_LOGITS>>>(b_out, out);

    // 9) h_last tail
    copy_hlast<<<BB, HD>>>(out + LOGITS_ELEMS);
}

// round 8
// speedup vs baseline: 1.9063x; 1.3219x over previous
#include <cuda_runtime.h>
#include <cuda_fp16.h>
#include <mma.h>
#include <math.h>
#include <stdint.h>

using namespace nvcuda;

// Problem constants
#define BB   16
#define TD   64
#define TE   64
#define HD   512
#define G3   1536
#define VV   32000
#define LOGITS_ELEMS (BB*TD*VV)   // 32768000

// ---------------- scratch (__device__ globals, no allocation) ----------------
__device__ float g_xp   [BB*TD*G3];
__device__ float g_part [2*16*BB*G3];
__device__ float g_dec  [BB*TD*HD];
__device__ float g_encp [BB*TE*HD];
__device__ float g_decp [BB*TD*HD];
__device__ float g_ctx  [BB*TD*HD];
__device__ float g_dense[BB*TD*HD];
__device__ float g_hlast[BB*HD];

// fp16 operands for the tensor-core logits GEMM (single-product, err ~3e-4)
__device__ __half g_Ah[BB*TD*HD];
__device__ __half g_Bh[(size_t)VV*HD];

__device__ unsigned int g_bar_cnt = 0;
__device__ unsigned int g_bar_gen = 0;

// ---------------- helpers (baseline-PTX only) ----------------
__device__ __forceinline__ uint32_t smem_u32(const void* p) {
    uint32_t a;
    asm("{ .reg .u64 t; cvta.to.shared.u64 t, %1; cvt.u32.u64 %0, t; }" : "=r"(a) : "l"(p));
    return a;
}
__device__ __forceinline__ void cp16(uint32_t s, const void* g) {
    asm volatile("cp.async.cg.shared.global [%0], [%1], 16;" :: "r"(s), "l"(g));
}

// ---------------- grid barrier ----------------
__device__ __forceinline__ void grid_barrier(unsigned int nblocks) {
    __syncthreads();
    if (threadIdx.x == 0) {
        __threadfence();
        unsigned int gen = atomicAdd(&g_bar_gen, 0u);
        __threadfence();
        unsigned int ticket = atomicAdd(&g_bar_cnt, 1u);
        if (ticket == nblocks - 1u) {
            atomicExch(&g_bar_cnt, 0u);
            __threadfence();
            atomicAdd(&g_bar_gen, 1u);
        } else {
            while (atomicAdd(&g_bar_gen, 0u) == gen) { }
        }
        __threadfence();
    }
    __syncthreads();
}

// ---------------- generic NT SGEMM (small GEMMs only) ----------------
#define FLAG_ACC  1
#define FLAG_TANH 2
__global__ void sgemm_nt(const float* __restrict__ A, int lda,
                         const float* __restrict__ B, int ldb,
                         const float* __restrict__ bias,
                         float* __restrict__ C, int ldc,
                         int K, int flags)
{
    __shared__ float As[16][64];
    __shared__ float Bs[16][64];
    const int bm = blockIdx.y * 64;
    const int bn = blockIdx.x * 64;
    const int tid = threadIdx.x;
    const int tr = tid >> 4;
    const int tc = tid & 15;
    const int lrow = tid >> 2;
    const int lcol = (tid & 3) * 4;

    float acc[4][4];
    #pragma unroll
    for (int i = 0; i < 4; i++)
        #pragma unroll
        for (int j = 0; j < 4; j++) acc[i][j] = 0.f;

    for (int k0 = 0; k0 < K; k0 += 16) {
        float4 av = *(const float4*)(A + (size_t)(bm + lrow) * lda + k0 + lcol);
        float4 bv = *(const float4*)(B + (size_t)(bn + lrow) * ldb + k0 + lcol);
        As[lcol + 0][lrow] = av.x; As[lcol + 1][lrow] = av.y;
        As[lcol + 2][lrow] = av.z; As[lcol + 3][lrow] = av.w;
        Bs[lcol + 0][lrow] = bv.x; Bs[lcol + 1][lrow] = bv.y;
        Bs[lcol + 2][lrow] = bv.z; Bs[lcol + 3][lrow] = bv.w;
        __syncthreads();
        #pragma unroll
        for (int kk = 0; kk < 16; kk++) {
            float a0 = As[kk][tr * 4 + 0], a1 = As[kk][tr * 4 + 1];
            float a2 = As[kk][tr * 4 + 2], a3 = As[kk][tr * 4 + 3];
            float b0 = Bs[kk][tc * 4 + 0], b1 = Bs[kk][tc * 4 + 1];
            float b2 = Bs[kk][tc * 4 + 2], b3 = Bs[kk][tc * 4 + 3];
            acc[0][0] += a0 * b0; acc[0][1] += a0 * b1; acc[0][2] += a0 * b2; acc[0][3] += a0 * b3;
            acc[1][0] += a1 * b0; acc[1][1] += a1 * b1; acc[1][2] += a1 * b2; acc[1][3] += a1 * b3;
            acc[2][0] += a2 * b0; acc[2][1] += a2 * b1; acc[2][2] += a2 * b2; acc[2][3] += a2 * b3;
            acc[3][0] += a3 * b0; acc[3][1] += a3 * b1; acc[3][2] += a3 * b2; acc[3][3] += a3 * b3;
        }
        __syncthreads();
    }

    #pragma unroll
    for (int i = 0; i < 4; i++) {
        int m = bm + tr * 4 + i;
        #pragma unroll
        for (int j = 0; j < 4; j++) {
            int n = bn + tc * 4 + j;
            float v = acc[i][j];
            if (flags & FLAG_ACC) v += C[(size_t)m * ldc + n];
            if (bias) v += bias[n];
            if (flags & FLAG_TANH) v = tanhf(v);
            C[(size_t)m * ldc + n] = v;
        }
    }
}

// ---------------- persistent GRU scan (unchanged, passing) ----------------
__global__ void gru_scan(const float* __restrict__ W_hh,
                         const float* __restrict__ b_hh,
                         const int*   __restrict__ lengths)
{
    __shared__ float sW[32 * 256];
    __shared__ float sh[32 * 16];

    const int tid    = threadIdx.x;
    const int gchunk = blockIdx.x / 16;
    const int ks     = blockIdx.x % 16;
    const int g0     = gchunk * 256;
    const int hs0    = ks * 32;
    const int gg     = g0 + tid;

    {
        const float4* wr = (const float4*)(W_hh + (size_t)gg * HD + hs0);
        #pragma unroll
        for (int q = 0; q < 8; q++) {
            float4 v = wr[q];
            sW[(q * 4 + 0) * 256 + tid] = v.x;
            sW[(q * 4 + 1) * 256 + tid] = v.y;
            sW[(q * 4 + 2) * 256 + tid] = v.z;
            sW[(q * 4 + 3) * 256 + tid] = v.w;
        }
    }
    sh[tid] = 0.f;
    sh[tid + 256] = 0.f;
    __syncthreads();

    for (int t = 0; t < TD; t++) {
        const int buf = t & 1;

        float acc[16];
        #pragma unroll
        for (int b = 0; b < 16; b++) acc[b] = 0.f;
        #pragma unroll
        for (int hrel = 0; hrel < 32; hrel++) {
            float w = sW[hrel * 256 + tid];
            const float4* hv = (const float4*)(sh + hrel * 16);
            float4 h0 = hv[0], h1 = hv[1], h2 = hv[2], h3 = hv[3];
            acc[0]  += w * h0.x; acc[1]  += w * h0.y; acc[2]  += w * h0.z; acc[3]  += w * h0.w;
            acc[4]  += w * h1.x; acc[5]  += w * h1.y; acc[6]  += w * h1.z; acc[7]  += w * h1.w;
            acc[8]  += w * h2.x; acc[9]  += w * h2.y; acc[10] += w * h2.z; acc[11] += w * h2.w;
            acc[12] += w * h3.x; acc[13] += w * h3.y; acc[14] += w * h3.z; acc[15] += w * h3.w;
        }
        {
            float* pbase = g_part + (size_t)(buf * 16 + ks) * (BB * G3);
            #pragma unroll
            for (int b = 0; b < 16; b++) pbase[(size_t)b * G3 + gg] = acc[b];
        }

        grid_barrier(96);

        #pragma unroll
        for (int i = 0; i < 2; i++) {
            int p    = tid + i * 256;
            int b    = p >> 5;
            int jrel = p & 31;
            int j    = hs0 + jrel;
            float rs = 0.f, zs = 0.f, ns = 0.f;
            const float* pb = g_part + (size_t)buf * 16 * BB * G3 + (size_t)b * G3;
            #pragma unroll
            for (int k2 = 0; k2 < 16; k2++) {
                const float* pp = pb + (size_t)k2 * (BB * G3);
                rs += pp[j];
                zs += pp[512 + j];
                ns += pp[1024 + j];
            }
            rs += b_hh[j];
            zs += b_hh[512 + j];
            ns += b_hh[1024 + j];
            const float* xr = g_xp + ((size_t)b * TD + t) * G3;
            float r = 1.f / (1.f + expf(-(xr[j] + rs)));
            float z = 1.f / (1.f + expf(-(xr[512 + j] + zs)));
            float n = tanhf(xr[1024 + j] + r * ns);
            float hold = sh[jrel * 16 + b];
            float hnew = (1.f - z) * n + z * hold;
            bool  valid = (t < lengths[b]);
            float hkeep = valid ? hnew : hold;
            sh[jrel * 16 + b] = hkeep;
            if (gchunk == 0) {
                g_dec[((size_t)b * TD + t) * HD + j] = valid ? hnew : 0.f;
                if (t == TD - 1) g_hlast[(size_t)b * HD + j] = hkeep;
            }
        }
        __syncthreads();
    }
}

// ---------------- attention (unchanged, passing) ----------------
__global__ void attn_kernel(const float* __restrict__ encp,
                            const float* __restrict__ decp,
                            const float* __restrict__ enc,
                            const int*   __restrict__ dlen,
                            const int*   __restrict__ elen,
                            const float* __restrict__ b_attn,
                            const float* __restrict__ v_w,
                            float* __restrict__ context)
{
    const int bd = blockIdx.x;
    const int b  = bd >> 6;
    const int d  = bd & 63;
    const int tid = threadIdx.x;

    __shared__ float s_dp[HD];
    __shared__ float s_vw[HD];
    __shared__ float s_en[TE];
    __shared__ float s_mx, s_ssum;

    float* ctx_out = context + (size_t)bd * HD;
    const int Dl = dlen[b];
    const int El = elen[b];

    if (d >= Dl) {
        for (int i = tid; i < HD; i += 256) ctx_out[i] = 0.f;
        return;
    }

    for (int i = tid; i < HD; i += 256) {
        s_dp[i] = decp[(size_t)bd * HD + i] + b_attn[i];
        s_vw[i] = v_w[i];
    }
    __syncthreads();

    const int warp = tid >> 5, lane = tid & 31;
    for (int e = warp; e < El; e += 8) {
        const float* ep = encp + ((size_t)b * TE + e) * HD;
        float sum = 0.f;
        #pragma unroll 4
        for (int h = lane; h < HD; h += 32)
            sum += tanhf(ep[h] + s_dp[h]) * s_vw[h];
        #pragma unroll
        for (int off = 16; off; off >>= 1)
            sum += __shfl_xor_sync(0xffffffffu, sum, off);
        if (lane == 0) s_en[e] = sum;
    }
    __syncthreads();

    if (tid < 32) {
        float mx = -1e30f;
        for (int e = lane; e < El; e += 32) mx = fmaxf(mx, s_en[e]);
        #pragma unroll
        for (int off = 16; off; off >>= 1)
            mx = fmaxf(mx, __shfl_xor_sync(0xffffffffu, mx, off));
        float ss = 0.f;
        for (int e = lane; e < El; e += 32) ss += expf(s_en[e] - mx);
        #pragma unroll
        for (int off = 16; off; off >>= 1)
            ss += __shfl_xor_sync(0xffffffffu, ss, off);
        if (lane == 0) { s_mx = mx; s_ssum = ss; }
    }
    __syncthreads();
    if (tid < TE) s_en[tid] = (tid < El) ? expf(s_en[tid] - s_mx) / s_ssum : 0.f;
    __syncthreads();

    for (int h = tid; h < HD; h += 256) {
        float a = 0.f;
        for (int e = 0; e < El; e++)
            a += s_en[e] * enc[((size_t)b * TE + e) * HD + h];
        ctx_out[h] = a;
    }
}

__global__ void copy_hlast(float* __restrict__ out)
{
    out[blockIdx.x * HD + threadIdx.x] = g_hlast[blockIdx.x * HD + threadIdx.x];
}

// ---------------- fp32 -> fp16 convert (8 elems/thread) ----------------
__global__ void conv_fp16(const float* __restrict__ src,
                          __half* __restrict__ dst, int n)
{
    int i = (blockIdx.x * 256 + threadIdx.x) * 8;
    if (i >= n) return;
    float4 v0 = *(const float4*)(src + i);
    float4 v1 = *(const float4*)(src + i + 4);
    __half2 h0 = __floats2half2_rn(v0.x, v0.y);
    __half2 h1 = __floats2half2_rn(v0.z, v0.w);
    __half2 h2 = __floats2half2_rn(v1.x, v1.y);
    __half2 h3 = __floats2half2_rn(v1.z, v1.w);
    __half2* dp = (__half2*)(dst + i);
    dp[0] = h0; dp[1] = h1; dp[2] = h2; dp[3] = h3;
}

// ---------------- wmma (HMMA) logits GEMM, fp16 single product ----------------
// D[1024,32000] = Ah*Bh^T + bias, fp32 accum. err ~3e-4 << 1e-3.
// CTA tile 128x128, K=512 in chunks of 32, cp.async double buffer, 2 CTAs/SM.
#define LBK   32
#define LDT   40                          // LBK + 8 pad (fp16 elems); row = 80 B
#define ARR_ELEMS (128 * LDT)             // 5120 halves per array
#define STAGE_ELEMS (2 * ARR_ELEMS)       // Ah|Bh = 10240 halves = 20480 B
#define SMEM_LOGITS 67584                 // epilogue staging 128 x 132 f32 dominates
#define LDC_S 132

__device__ __forceinline__ void load_stage_logits(int tid, int mt, int nt, int c,
                                                  uint32_t smbase, int s)
{
    const __half* srcs[2] = {
        g_Ah + (size_t)mt * 128 * HD,
        g_Bh + (size_t)nt * 128 * HD
    };
    #pragma unroll
    for (int arr = 0; arr < 2; arr++) {
        #pragma unroll
        for (int it = 0; it < 2; it++) {
            int i  = tid + it * 256;        // 0..511 : 128 rows x 4 float4s
            int r  = i >> 2;
            int c4 = i & 3;
            const void* src = srcs[arr] + (size_t)r * HD + c * LBK + c4 * 8;
            uint32_t dst = smbase + (uint32_t)(s * STAGE_ELEMS + arr * ARR_ELEMS) * 2u
                         + (uint32_t)(r * (LDT * 2) + c4 * 16);
            cp16(dst, src);
        }
    }
    asm volatile("cp.async.commit_group;" ::: "memory");
}

__global__ void __launch_bounds__(256, 2) logits_wmma(const float* __restrict__ b_out,
                                                      float* __restrict__ out)
{
    extern __shared__ __align__(16) char dynsmem[];
    __half* sm = (__half*)dynsmem;
    const uint32_t smbase = smem_u32(dynsmem);

    const int tid = threadIdx.x;
    const int wid = tid >> 5;
    const int nt = blockIdx.x;      // 0..249
    const int mt = blockIdx.y;      // 0..7
    const int warp_m = wid >> 2;    // 0..1
    const int warp_n = wid & 3;     // 0..3

    wmma::fragment<wmma::accumulator, 16, 16, 16, float> acc[4][2];
    #pragma unroll
    for (int i = 0; i < 4; i++)
        #pragma unroll
        for (int j = 0; j < 2; j++)
            wmma::fill_fragment(acc[i][j], 0.f);

    // prologue
    load_stage_logits(tid, mt, nt, 0, smbase, 0);
    load_stage_logits(tid, mt, nt, 1, smbase, 1);

    for (int c = 0; c < 16; c++) {
        const int s = c & 1;
        if (c < 15) asm volatile("cp.async.wait_group 1;" ::: "memory");
        else        asm volatile("cp.async.wait_group 0;" ::: "memory");
        __syncthreads();

        const __half* As = sm + s * STAGE_ELEMS;
        const __half* Bs = As + ARR_ELEMS;

        #pragma unroll
        for (int kk = 0; kk < LBK; kk += 16) {
            wmma::fragment<wmma::matrix_a, 16, 16, 16, __half, wmma::row_major> a[4];
            wmma::fragment<wmma::matrix_b, 16, 16, 16, __half, wmma::col_major> b[2];
            #pragma unroll
            for (int i = 0; i < 4; i++)
                wmma::load_matrix_sync(a[i], As + (warp_m * 64 + i * 16) * LDT + kk, LDT);
            #pragma unroll
            for (int j = 0; j < 2; j++)
                wmma::load_matrix_sync(b[j], Bs + (warp_n * 32 + j * 16) * LDT + kk, LDT);
            #pragma unroll
            for (int i = 0; i < 4; i++)
                #pragma unroll
                for (int j = 0; j < 2; j++)
                    wmma::mma_sync(acc[i][j], a[i], b[j], acc[i][j]);
        }
        __syncthreads();

        if (c + 2 < 16) load_stage_logits(tid, mt, nt, c + 2, smbase, s);
    }

    // epilogue: stage fp32 result in smem, add bias, write out
    __syncthreads();
    float* cs = (float*)dynsmem;   // 128 x LDC_S
    #pragma unroll
    for (int i = 0; i < 4; i++)
        #pragma unroll
        for (int j = 0; j < 2; j++)
            wmma::store_matrix_sync(cs + (warp_m * 64 + i * 16) * LDC_S + (warp_n * 32 + j * 16),
                                    acc[i][j], LDC_S, wmma::mem_row_major);
    __syncthreads();

    const int n0 = nt * 128;
    #pragma unroll
    for (int it = 0; it < 16; it++) {
        int i  = tid + it * 256;      // 0..4095 : 128 rows x 32 float4s
        int r  = i >> 5;
        int c4 = (i & 31) * 4;
        float4 v = *(float4*)(cs + r * LDC_S + c4);
        v.x += b_out[n0 + c4 + 0];
        v.y += b_out[n0 + c4 + 1];
        v.z += b_out[n0 + c4 + 2];
        v.w += b_out[n0 + c4 + 3];
        *(float4*)(out + (size_t)(mt * 128 + r) * VV + n0 + c4) = v;
    }
}

// ---------------- launch ----------------
extern "C" void kernel_launch(void* const* d_in, const int* in_sizes, int n_in,
                              void* d_out, int out_size)
{
    const float* x      = (const float*)d_in[0];
    const int*   inlen  = (const int*)  d_in[1];
    const float* enc    = (const float*)d_in[2];
    const int*   enclen = (const int*)  d_in[3];
    const float* W_ih   = (const float*)d_in[4];
    const float* W_hh   = (const float*)d_in[5];
    const float* b_ih   = (const float*)d_in[6];
    const float* b_hh   = (const float*)d_in[7];
    const float* W_attn = (const float*)d_in[8];
    const float* b_attn = (const float*)d_in[9];
    const float* v_w    = (const float*)d_in[10];
    const float* W_dense= (const float*)d_in[12];
    const float* b_dense= (const float*)d_in[13];
    const float* W_out  = (const float*)d_in[14];
    const float* b_out  = (const float*)d_in[15];

    float* out = (float*)d_out;

    float* xp    = nullptr; cudaGetSymbolAddress((void**)&xp,    g_xp);
    float* dec   = nullptr; cudaGetSymbolAddress((void**)&dec,   g_dec);
    float* encp  = nullptr; cudaGetSymbolAddress((void**)&encp,  g_encp);
    float* decp  = nullptr; cudaGetSymbolAddress((void**)&decp,  g_decp);
    float* ctx   = nullptr; cudaGetSymbolAddress((void**)&ctx,   g_ctx);
    float* dense = nullptr; cudaGetSymbolAddress((void**)&dense, g_dense);
    __half* Ah = nullptr; cudaGetSymbolAddress((void**)&Ah, g_Ah);
    __half* Bh = nullptr; cudaGetSymbolAddress((void**)&Bh, g_Bh);

    cudaFuncSetAttribute(logits_wmma, cudaFuncAttributeMaxDynamicSharedMemorySize, SMEM_LOGITS);

    // 1) x_proj
    sgemm_nt<<<dim3(G3 / 64, (BB * TD) / 64), 256>>>(x, HD, W_ih, HD, b_ih, xp, G3, HD, 0);

    // W_out fp16 convert (independent of everything upstream)
    conv_fp16<<<((size_t)VV * HD) / 2048, 256>>>(W_out, Bh, VV * HD);

    // 2) GRU scan
    gru_scan<<<96, 256>>>(W_hh, b_hh, inlen);

    // 3,4) attention projections
    sgemm_nt<<<dim3(HD / 64, (BB * TE) / 64), 256>>>(enc, HD, W_attn,      2 * HD, nullptr, encp, HD, HD, 0);
    sgemm_nt<<<dim3(HD / 64, (BB * TD) / 64), 256>>>(dec, HD, W_attn + HD, 2 * HD, nullptr, decp, HD, HD, 0);

    // 5) attention
    attn_kernel<<<BB * TD, 256>>>(encp, decp, enc, inlen, enclen, b_attn, v_w, ctx);

    // 6,7) dense
    sgemm_nt<<<dim3(HD / 64, (BB * TD) / 64), 256>>>(dec, HD, W_dense,      2 * HD, nullptr, dense, HD, HD, 0);
    sgemm_nt<<<dim3(HD / 64, (BB * TD) / 64), 256>>>(ctx, HD, W_dense + HD, 2 * HD, b_dense, dense, HD, HD, FLAG_ACC | FLAG_TANH);

    // 8) logits via wmma/HMMA fp16 single product
    conv_fp16<<<(BB * TD * HD) / 2048, 256>>>(dense, Ah, BB * TD * HD);
    logits_wmma<<<dim3(VV / 128, (BB * TD) / 128), 256, SMEM_LOGITS>>>(b_out, out);

    // 9) h_last tail
    copy_hlast<<<BB, HD>>>(out + LOGITS_ELEMS);
}

// round 9
// speedup vs baseline: 2.0237x; 1.0616x over previous
#include <cuda_runtime.h>
#include <cuda_fp16.h>
#include <mma.h>
#include <math.h>
#include <stdint.h>

using namespace nvcuda;

// Problem constants
#define BB   16
#define TD   64
#define TE   64
#define HD   512
#define G3   1536
#define VV   32000
#define LOGITS_ELEMS (BB*TD*VV)   // 32768000

// ---------------- scratch (__device__ globals, no allocation) ----------------
__device__ float g_xp   [BB*TD*G3];
__device__ float g_part [2*16*BB*G3];
__device__ float g_dec  [BB*TD*HD];
__device__ float g_encp [BB*TE*HD];
__device__ float g_decp [BB*TD*HD];
__device__ float g_ctx  [BB*TD*HD];
__device__ float g_dense[BB*TD*HD];
__device__ float g_hlast[BB*HD];

// fp16 operands for the tensor-core logits GEMM (single-product, err ~3e-4)
__device__ __half g_Ah[BB*TD*HD];
__device__ __half g_Bh[(size_t)VV*HD];

__device__ unsigned int g_bar_cnt = 0;
__device__ unsigned int g_bar_gen = 0;

// ---------------- helpers (baseline-PTX only) ----------------
__device__ __forceinline__ uint32_t smem_u32(const void* p) {
    uint32_t a;
    asm("{ .reg .u64 t; cvta.to.shared.u64 t, %1; cvt.u32.u64 %0, t; }" : "=r"(a) : "l"(p));
    return a;
}
__device__ __forceinline__ void cp16(uint32_t s, const void* g) {
    asm volatile("cp.async.cg.shared.global [%0], [%1], 16;" :: "r"(s), "l"(g));
}

// ---------------- grid barrier (volatile poll + nanosleep backoff) ----------------
__device__ __forceinline__ void grid_barrier(unsigned int nblocks) {
    __syncthreads();
    if (threadIdx.x == 0) {
        volatile unsigned int* genp = (volatile unsigned int*)&g_bar_gen;
        unsigned int gen = *genp;
        __threadfence();
        unsigned int ticket = atomicAdd(&g_bar_cnt, 1u);
        if (ticket == nblocks - 1u) {
            g_bar_cnt = 0;
            __threadfence();
            *genp = gen + 1u;
        } else {
            while (*genp == gen) { __nanosleep(64); }
        }
        __threadfence();
    }
    __syncthreads();
}

// ---------------- generic NT SGEMM (small GEMMs only) ----------------
#define FLAG_ACC  1
#define FLAG_TANH 2
__global__ void sgemm_nt(const float* __restrict__ A, int lda,
                         const float* __restrict__ B, int ldb,
                         const float* __restrict__ bias,
                         float* __restrict__ C, int ldc,
                         int K, int flags)
{
    __shared__ float As[16][64];
    __shared__ float Bs[16][64];
    const int bm = blockIdx.y * 64;
    const int bn = blockIdx.x * 64;
    const int tid = threadIdx.x;
    const int tr = tid >> 4;
    const int tc = tid & 15;
    const int lrow = tid >> 2;
    const int lcol = (tid & 3) * 4;

    float acc[4][4];
    #pragma unroll
    for (int i = 0; i < 4; i++)
        #pragma unroll
        for (int j = 0; j < 4; j++) acc[i][j] = 0.f;

    for (int k0 = 0; k0 < K; k0 += 16) {
        float4 av = *(const float4*)(A + (size_t)(bm + lrow) * lda + k0 + lcol);
        float4 bv = *(const float4*)(B + (size_t)(bn + lrow) * ldb + k0 + lcol);
        As[lcol + 0][lrow] = av.x; As[lcol + 1][lrow] = av.y;
        As[lcol + 2][lrow] = av.z; As[lcol + 3][lrow] = av.w;
        Bs[lcol + 0][lrow] = bv.x; Bs[lcol + 1][lrow] = bv.y;
        Bs[lcol + 2][lrow] = bv.z; Bs[lcol + 3][lrow] = bv.w;
        __syncthreads();
        #pragma unroll
        for (int kk = 0; kk < 16; kk++) {
            float a0 = As[kk][tr * 4 + 0], a1 = As[kk][tr * 4 + 1];
            float a2 = As[kk][tr * 4 + 2], a3 = As[kk][tr * 4 + 3];
            float b0 = Bs[kk][tc * 4 + 0], b1 = Bs[kk][tc * 4 + 1];
            float b2 = Bs[kk][tc * 4 + 2], b3 = Bs[kk][tc * 4 + 3];
            acc[0][0] += a0 * b0; acc[0][1] += a0 * b1; acc[0][2] += a0 * b2; acc[0][3] += a0 * b3;
            acc[1][0] += a1 * b0; acc[1][1] += a1 * b1; acc[1][2] += a1 * b2; acc[1][3] += a1 * b3;
            acc[2][0] += a2 * b0; acc[2][1] += a2 * b1; acc[2][2] += a2 * b2; acc[2][3] += a2 * b3;
            acc[3][0] += a3 * b0; acc[3][1] += a3 * b1; acc[3][2] += a3 * b2; acc[3][3] += a3 * b3;
        }
        __syncthreads();
    }

    #pragma unroll
    for (int i = 0; i < 4; i++) {
        int m = bm + tr * 4 + i;
        #pragma unroll
        for (int j = 0; j < 4; j++) {
            int n = bn + tc * 4 + j;
            float v = acc[i][j];
            if (flags & FLAG_ACC) v += C[(size_t)m * ldc + n];
            if (bias) v += bias[n];
            if (flags & FLAG_TANH) v = tanhf(v);
            C[(size_t)m * ldc + n] = v;
        }
    }
}

// ---------------- persistent GRU scan ----------------
__global__ void gru_scan(const float* __restrict__ W_hh,
                         const float* __restrict__ b_hh,
                         const int*   __restrict__ lengths)
{
    __shared__ float sW[32 * 256];
    __shared__ float sh[32 * 16];

    const int tid    = threadIdx.x;
    const int gchunk = blockIdx.x / 16;
    const int ks     = blockIdx.x % 16;
    const int g0     = gchunk * 256;
    const int hs0    = ks * 32;
    const int gg     = g0 + tid;

    {
        const float4* wr = (const float4*)(W_hh + (size_t)gg * HD + hs0);
        #pragma unroll
        for (int q = 0; q < 8; q++) {
            float4 v = wr[q];
            sW[(q * 4 + 0) * 256 + tid] = v.x;
            sW[(q * 4 + 1) * 256 + tid] = v.y;
            sW[(q * 4 + 2) * 256 + tid] = v.z;
            sW[(q * 4 + 3) * 256 + tid] = v.w;
        }
    }
    sh[tid] = 0.f;
    sh[tid + 256] = 0.f;
    __syncthreads();

    for (int t = 0; t < TD; t++) {
        const int buf = t & 1;

        float acc[16];
        #pragma unroll
        for (int b = 0; b < 16; b++) acc[b] = 0.f;
        #pragma unroll
        for (int hrel = 0; hrel < 32; hrel++) {
            float w = sW[hrel * 256 + tid];
            const float4* hv = (const float4*)(sh + hrel * 16);
            float4 h0 = hv[0], h1 = hv[1], h2 = hv[2], h3 = hv[3];
            acc[0]  += w * h0.x; acc[1]  += w * h0.y; acc[2]  += w * h0.z; acc[3]  += w * h0.w;
            acc[4]  += w * h1.x; acc[5]  += w * h1.y; acc[6]  += w * h1.z; acc[7]  += w * h1.w;
            acc[8]  += w * h2.x; acc[9]  += w * h2.y; acc[10] += w * h2.z; acc[11] += w * h2.w;
            acc[12] += w * h3.x; acc[13] += w * h3.y; acc[14] += w * h3.z; acc[15] += w * h3.w;
        }
        {
            float* pbase = g_part + (size_t)(buf * 16 + ks) * (BB * G3);
            #pragma unroll
            for (int b = 0; b < 16; b++) pbase[(size_t)b * G3 + gg] = acc[b];
        }

        grid_barrier(96);

        #pragma unroll
        for (int i = 0; i < 2; i++) {
            int p    = tid + i * 256;
            int b    = p >> 5;
            int jrel = p & 31;
            int j    = hs0 + jrel;
            float rs = 0.f, zs = 0.f, ns = 0.f;
            const float* pb = g_part + (size_t)buf * 16 * BB * G3 + (size_t)b * G3;
            #pragma unroll
            for (int k2 = 0; k2 < 16; k2++) {
                const float* pp = pb + (size_t)k2 * (BB * G3);
                rs += pp[j];
                zs += pp[512 + j];
                ns += pp[1024 + j];
            }
            rs += b_hh[j];
            zs += b_hh[512 + j];
            ns += b_hh[1024 + j];
            const float* xr = g_xp + ((size_t)b * TD + t) * G3;
            float r = 1.f / (1.f + expf(-(xr[j] + rs)));
            float z = 1.f / (1.f + expf(-(xr[512 + j] + zs)));
            float n = tanhf(xr[1024 + j] + r * ns);
            float hold = sh[jrel * 16 + b];
            float hnew = (1.f - z) * n + z * hold;
            bool  valid = (t < lengths[b]);
            float hkeep = valid ? hnew : hold;
            sh[jrel * 16 + b] = hkeep;
            if (gchunk == 0) {
                g_dec[((size_t)b * TD + t) * HD + j] = valid ? hnew : 0.f;
                if (t == TD - 1) g_hlast[(size_t)b * HD + j] = hkeep;
            }
        }
        __syncthreads();
    }
}

// ---------------- attention (unchanged, passing) ----------------
__global__ void attn_kernel(const float* __restrict__ encp,
                            const float* __restrict__ decp,
                            const float* __restrict__ enc,
                            const int*   __restrict__ dlen,
                            const int*   __restrict__ elen,
                            const float* __restrict__ b_attn,
                            const float* __restrict__ v_w,
                            float* __restrict__ context)
{
    const int bd = blockIdx.x;
    const int b  = bd >> 6;
    const int d  = bd & 63;
    const int tid = threadIdx.x;

    __shared__ float s_dp[HD];
    __shared__ float s_vw[HD];
    __shared__ float s_en[TE];
    __shared__ float s_mx, s_ssum;

    float* ctx_out = context + (size_t)bd * HD;
    const int Dl = dlen[b];
    const int El = elen[b];

    if (d >= Dl) {
        for (int i = tid; i < HD; i += 256) ctx_out[i] = 0.f;
        return;
    }

    for (int i = tid; i < HD; i += 256) {
        s_dp[i] = decp[(size_t)bd * HD + i] + b_attn[i];
        s_vw[i] = v_w[i];
    }
    __syncthreads();

    const int warp = tid >> 5, lane = tid & 31;
    for (int e = warp; e < El; e += 8) {
        const float* ep = encp + ((size_t)b * TE + e) * HD;
        float sum = 0.f;
        #pragma unroll 4
        for (int h = lane; h < HD; h += 32)
            sum += tanhf(ep[h] + s_dp[h]) * s_vw[h];
        #pragma unroll
        for (int off = 16; off; off >>= 1)
            sum += __shfl_xor_sync(0xffffffffu, sum, off);
        if (lane == 0) s_en[e] = sum;
    }
    __syncthreads();

    if (tid < 32) {
        float mx = -1e30f;
        for (int e = lane; e < El; e += 32) mx = fmaxf(mx, s_en[e]);
        #pragma unroll
        for (int off = 16; off; off >>= 1)
            mx = fmaxf(mx, __shfl_xor_sync(0xffffffffu, mx, off));
        float ss = 0.f;
        for (int e = lane; e < El; e += 32) ss += expf(s_en[e] - mx);
        #pragma unroll
        for (int off = 16; off; off >>= 1)
            ss += __shfl_xor_sync(0xffffffffu, ss, off);
        if (lane == 0) { s_mx = mx; s_ssum = ss; }
    }
    __syncthreads();
    if (tid < TE) s_en[tid] = (tid < El) ? expf(s_en[tid] - s_mx) / s_ssum : 0.f;
    __syncthreads();

    for (int h = tid; h < HD; h += 256) {
        float a = 0.f;
        for (int e = 0; e < El; e++)
            a += s_en[e] * enc[((size_t)b * TE + e) * HD + h];
        ctx_out[h] = a;
    }
}

__global__ void copy_hlast(float* __restrict__ out)
{
    out[blockIdx.x * HD + threadIdx.x] = g_hlast[blockIdx.x * HD + threadIdx.x];
}

// ---------------- fp32 -> fp16 convert (8 elems/thread) ----------------
__global__ void conv_fp16(const float* __restrict__ src,
                          __half* __restrict__ dst, int n)
{
    int i = (blockIdx.x * 256 + threadIdx.x) * 8;
    if (i >= n) return;
    float4 v0 = *(const float4*)(src + i);
    float4 v1 = *(const float4*)(src + i + 4);
    __half2 h0 = __floats2half2_rn(v0.x, v0.y);
    __half2 h1 = __floats2half2_rn(v0.z, v0.w);
    __half2 h2 = __floats2half2_rn(v1.x, v1.y);
    __half2 h3 = __floats2half2_rn(v1.z, v1.w);
    __half2* dp = (__half2*)(dst + i);
    dp[0] = h0; dp[1] = h1; dp[2] = h2; dp[3] = h3;
}

// ---------------- wmma (HMMA) logits GEMM, fp16 single product ----------------
// D[1024,32000] = Ah*Bh^T + bias, fp32 accum.
// CTA tile 128x128, 4 warps (2x2), warp tile 64x64 (4x4 wmma frags) — 2.0 MMA/frag-load.
// K=512 in chunks of 32, cp.async double buffer, 2 CTAs/SM.
#define LBK   32
#define LDT   40                          // LBK + 8 pad (fp16 elems); row = 80 B
#define ARR_ELEMS (128 * LDT)             // 5120 halves per array
#define STAGE_ELEMS (2 * ARR_ELEMS)       // Ah|Bh = 10240 halves = 20480 B
#define LDC_W 68                          // per-warp epilogue staging (64 x 68 f32)
#define SMEM_LOGITS (4 * 64 * LDC_W * 4)  // 69632 B (covers 2 stages = 40960 too)

__device__ __forceinline__ void load_stage_logits(int tid, int mt, int nt, int c,
                                                  uint32_t smbase, int s)
{
    const __half* srcs[2] = {
        g_Ah + (size_t)mt * 128 * HD,
        g_Bh + (size_t)nt * 128 * HD
    };
    #pragma unroll
    for (int arr = 0; arr < 2; arr++) {
        #pragma unroll
        for (int it = 0; it < 4; it++) {
            int i  = tid + it * 128;        // 0..511 : 128 rows x 4 float4s
            int r  = i >> 2;
            int c4 = i & 3;
            const void* src = srcs[arr] + (size_t)r * HD + c * LBK + c4 * 8;
            uint32_t dst = smbase + (uint32_t)(s * STAGE_ELEMS + arr * ARR_ELEMS) * 2u
                         + (uint32_t)(r * (LDT * 2) + c4 * 16);
            cp16(dst, src);
        }
    }
    asm volatile("cp.async.commit_group;" ::: "memory");
}

__global__ void __launch_bounds__(128, 2) logits_wmma(const float* __restrict__ b_out,
                                                      float* __restrict__ out)
{
    extern __shared__ __align__(16) char dynsmem[];
    __half* sm = (__half*)dynsmem;
    const uint32_t smbase = smem_u32(dynsmem);

    const int tid = threadIdx.x;
    const int wid = tid >> 5, lane = tid & 31;
    const int nt = blockIdx.x;      // 0..249
    const int mt = blockIdx.y;      // 0..7
    const int warp_m = wid >> 1;    // 0..1
    const int warp_n = wid & 1;     // 0..1

    wmma::fragment<wmma::accumulator, 16, 16, 16, float> acc[4][4];
    #pragma unroll
    for (int i = 0; i < 4; i++)
        #pragma unroll
        for (int j = 0; j < 4; j++)
            wmma::fill_fragment(acc[i][j], 0.f);

    // prologue
    load_stage_logits(tid, mt, nt, 0, smbase, 0);
    load_stage_logits(tid, mt, nt, 1, smbase, 1);

    for (int c = 0; c < 16; c++) {
        const int s = c & 1;
        if (c < 15) asm volatile("cp.async.wait_group 1;" ::: "memory");
        else        asm volatile("cp.async.wait_group 0;" ::: "memory");
        __syncthreads();

        const __half* As = sm + s * STAGE_ELEMS;
        const __half* Bs = As + ARR_ELEMS;

        #pragma unroll
        for (int kk = 0; kk < LBK; kk += 16) {
            wmma::fragment<wmma::matrix_a, 16, 16, 16, __half, wmma::row_major> a[4];
            wmma::fragment<wmma::matrix_b, 16, 16, 16, __half, wmma::col_major> b[4];
            #pragma unroll
            for (int i = 0; i < 4; i++)
                wmma::load_matrix_sync(a[i], As + (warp_m * 64 + i * 16) * LDT + kk, LDT);
            #pragma unroll
            for (int j = 0; j < 4; j++)
                wmma::load_matrix_sync(b[j], Bs + (warp_n * 64 + j * 16) * LDT + kk, LDT);
            #pragma unroll
            for (int i = 0; i < 4; i++)
                #pragma unroll
                for (int j = 0; j < 4; j++)
                    wmma::mma_sync(acc[i][j], a[i], b[j], acc[i][j]);
        }
        __syncthreads();

        if (c + 2 < 16) load_stage_logits(tid, mt, nt, c + 2, smbase, s);
    }

    // epilogue: per-warp fp32 staging (reuses stage smem), bias add, direct store
    __syncthreads();
    float* ws = (float*)dynsmem + wid * 64 * LDC_W;
    #pragma unroll
    for (int i = 0; i < 4; i++)
        #pragma unroll
        for (int j = 0; j < 4; j++)
            wmma::store_matrix_sync(ws + i * 16 * LDC_W + j * 16, acc[i][j],
                                    LDC_W, wmma::mem_row_major);
    __syncwarp();

    const int row0 = mt * 128 + warp_m * 64;
    const int n0   = nt * 128 + warp_n * 64;
    #pragma unroll
    for (int it = 0; it < 32; it++) {
        int idx = lane + it * 32;        // 0..1023 : 64 rows x 16 float4s
        int r   = idx >> 4;
        int c4  = (idx & 15) * 4;
        float4 v = *(float4*)(ws + r * LDC_W + c4);
        v.x += b_out[n0 + c4 + 0];
        v.y += b_out[n0 + c4 + 1];
        v.z += b_out[n0 + c4 + 2];
        v.w += b_out[n0 + c4 + 3];
        *(float4*)(out + (size_t)(row0 + r) * VV + n0 + c4) = v;
    }
}

// ---------------- launch ----------------
extern "C" void kernel_launch(void* const* d_in, const int* in_sizes, int n_in,
                              void* d_out, int out_size)
{
    const float* x      = (const float*)d_in[0];
    const int*   inlen  = (const int*)  d_in[1];
    const float* enc    = (const float*)d_in[2];
    const int*   enclen = (const int*)  d_in[3];
    const float* W_ih   = (const float*)d_in[4];
    const float* W_hh   = (const float*)d_in[5];
    const float* b_ih   = (const float*)d_in[6];
    const float* b_hh   = (const float*)d_in[7];
    const float* W_attn = (const float*)d_in[8];
    const float* b_attn = (const float*)d_in[9];
    const float* v_w    = (const float*)d_in[10];
    const float* W_dense= (const float*)d_in[12];
    const float* b_dense= (const float*)d_in[13];
    const float* W_out  = (const float*)d_in[14];
    const float* b_out  = (const float*)d_in[15];

    float* out = (float*)d_out;

    float* xp    = nullptr; cudaGetSymbolAddress((void**)&xp,    g_xp);
    float* dec   = nullptr; cudaGetSymbolAddress((void**)&dec,   g_dec);
    float* encp  = nullptr; cudaGetSymbolAddress((void**)&encp,  g_encp);
    float* decp  = nullptr; cudaGetSymbolAddress((void**)&decp,  g_decp);
    float* ctx   = nullptr; cudaGetSymbolAddress((void**)&ctx,   g_ctx);
    float* dense = nullptr; cudaGetSymbolAddress((void**)&dense, g_dense);
    __half* Ah = nullptr; cudaGetSymbolAddress((void**)&Ah, g_Ah);
    __half* Bh = nullptr; cudaGetSymbolAddress((void**)&Bh, g_Bh);

    cudaFuncSetAttribute(logits_wmma, cudaFuncAttributeMaxDynamicSharedMemorySize, SMEM_LOGITS);

    // 1) x_proj
    sgemm_nt<<<dim3(G3 / 64, (BB * TD) / 64), 256>>>(x, HD, W_ih, HD, b_ih, xp, G3, HD, 0);

    // W_out fp16 convert (independent of everything upstream)
    conv_fp16<<<((size_t)VV * HD) / 2048, 256>>>(W_out, Bh, VV * HD);

    // 2) GRU scan
    gru_scan<<<96, 256>>>(W_hh, b_hh, inlen);

    // 3,4) attention projections
    sgemm_nt<<<dim3(HD / 64, (BB * TE) / 64), 256>>>(enc, HD, W_attn,      2 * HD, nullptr, encp, HD, HD, 0);
    sgemm_nt<<<dim3(HD / 64, (BB * TD) / 64), 256>>>(dec, HD, W_attn + HD, 2 * HD, nullptr, decp, HD, HD, 0);

    // 5) attention
    attn_kernel<<<BB * TD, 256>>>(encp, decp, enc, inlen, enclen, b_attn, v_w, ctx);

    // 6,7) dense
    sgemm_nt<<<dim3(HD / 64, (BB * TD) / 64), 256>>>(dec, HD, W_dense,      2 * HD, nullptr, dense, HD, HD, 0);
    sgemm_nt<<<dim3(HD / 64, (BB * TD) / 64), 256>>>(ctx, HD, W_dense + HD, 2 * HD, b_dense, dense, HD, HD, FLAG_ACC | FLAG_TANH);

    // 8) logits via wmma/HMMA fp16 single product
    conv_fp16<<<(BB * TD * HD) / 2048, 256>>>(dense, Ah, BB * TD * HD);
    logits_wmma<<<dim3(VV / 128, (BB * TD) / 128), 128, SMEM_LOGITS>>>(b_out, out);

    // 9) h_last tail
    copy_hlast<<<BB, HD>>>(out + LOGITS_ELEMS);
}

// round 10
// speedup vs baseline: 2.2960x; 1.1345x over previous
#include <cuda_runtime.h>
#include <cuda_fp16.h>
#include <mma.h>
#include <math.h>
#include <stdint.h>

using namespace nvcuda;

// Problem constants
#define BB   16
#define TD   64
#define TE   64
#define HD   512
#define G3   1536
#define VV   32000
#define LOGITS_ELEMS (BB*TD*VV)   // 32768000

// ---------------- scratch (__device__ globals, no allocation) ----------------
__device__ float g_xp   [BB*TD*G3];
__device__ float g_part [2*16*BB*G3];
__device__ float g_dec  [BB*TD*HD];
__device__ float g_encp [BB*TE*HD];
__device__ float g_decp [BB*TD*HD];
__device__ float g_ctx  [BB*TD*HD];
__device__ float g_hlast[BB*HD];

// fp16 operands
__device__ __half g_Ah  [BB*TD*HD];          // dense output (tanh), feeds logits
__device__ __half g_Bh  [(size_t)VV*HD];     // W_out
__device__ __half g_ench[BB*TE*HD];          // enc
__device__ __half g_cat [BB*TD*2*HD];        // [dec | ctx] fp16
__device__ __half g_Wae [HD*HD];             // W_attn[:, :512]
__device__ __half g_Wad [HD*HD];             // W_attn[:, 512:]
__device__ __half g_Wdh [HD*2*HD];           // W_dense

// barrier state (persists across graph replays; epoch-based)
__device__ volatile unsigned int g_flags[96];
__device__ volatile unsigned int g_rel;

// ---------------- helpers (baseline-PTX only) ----------------
__device__ __forceinline__ uint32_t smem_u32(const void* p) {
    uint32_t a;
    asm("{ .reg .u64 t; cvta.to.shared.u64 t, %1; cvt.u32.u64 %0, t; }" : "=r"(a) : "l"(p));
    return a;
}
__device__ __forceinline__ void cp16(uint32_t s, const void* g) {
    asm volatile("cp.async.cg.shared.global [%0], [%1], 16;" :: "r"(s), "l"(g));
}

// ---------------- generic NT SGEMM (x_proj only) ----------------
__global__ void sgemm_nt(const float* __restrict__ A, int lda,
                         const float* __restrict__ B, int ldb,
                         const float* __restrict__ bias,
                         float* __restrict__ C, int ldc, int K)
{
    __shared__ float As[16][64];
    __shared__ float Bs[16][64];
    const int bm = blockIdx.y * 64;
    const int bn = blockIdx.x * 64;
    const int tid = threadIdx.x;
    const int tr = tid >> 4;
    const int tc = tid & 15;
    const int lrow = tid >> 2;
    const int lcol = (tid & 3) * 4;

    float acc[4][4];
    #pragma unroll
    for (int i = 0; i < 4; i++)
        #pragma unroll
        for (int j = 0; j < 4; j++) acc[i][j] = 0.f;

    for (int k0 = 0; k0 < K; k0 += 16) {
        float4 av = *(const float4*)(A + (size_t)(bm + lrow) * lda + k0 + lcol);
        float4 bv = *(const float4*)(B + (size_t)(bn + lrow) * ldb + k0 + lcol);
        As[lcol + 0][lrow] = av.x; As[lcol + 1][lrow] = av.y;
        As[lcol + 2][lrow] = av.z; As[lcol + 3][lrow] = av.w;
        Bs[lcol + 0][lrow] = bv.x; Bs[lcol + 1][lrow] = bv.y;
        Bs[lcol + 2][lrow] = bv.z; Bs[lcol + 3][lrow] = bv.w;
        __syncthreads();
        #pragma unroll
        for (int kk = 0; kk < 16; kk++) {
            float a0 = As[kk][tr * 4 + 0], a1 = As[kk][tr * 4 + 1];
            float a2 = As[kk][tr * 4 + 2], a3 = As[kk][tr * 4 + 3];
            float b0 = Bs[kk][tc * 4 + 0], b1 = Bs[kk][tc * 4 + 1];
            float b2 = Bs[kk][tc * 4 + 2], b3 = Bs[kk][tc * 4 + 3];
            acc[0][0] += a0 * b0; acc[0][1] += a0 * b1; acc[0][2] += a0 * b2; acc[0][3] += a0 * b3;
            acc[1][0] += a1 * b0; acc[1][1] += a1 * b1; acc[1][2] += a1 * b2; acc[1][3] += a1 * b3;
            acc[2][0] += a2 * b0; acc[2][1] += a2 * b1; acc[2][2] += a2 * b2; acc[2][3] += a2 * b3;
            acc[3][0] += a3 * b0; acc[3][1] += a3 * b1; acc[3][2] += a3 * b2; acc[3][3] += a3 * b3;
        }
        __syncthreads();
    }

    #pragma unroll
    for (int i = 0; i < 4; i++) {
        int m = bm + tr * 4 + i;
        #pragma unroll
        for (int j = 0; j < 4; j++) {
            int n = bn + tc * 4 + j;
            C[(size_t)m * ldc + n] = acc[i][j] + bias[n];
        }
    }
}

// ---------------- persistent GRU scan (flag-array barrier, no atomics) ----------------
__global__ void gru_scan(const float* __restrict__ W_hh,
                         const float* __restrict__ b_hh,
                         const int*   __restrict__ lengths)
{
    __shared__ float sW[32 * 256];
    __shared__ float sh[32 * 16];

    const int tid    = threadIdx.x;
    const int gchunk = blockIdx.x / 16;
    const int ks     = blockIdx.x % 16;
    const int g0     = gchunk * 256;
    const int hs0    = ks * 32;
    const int gg     = g0 + tid;

    // epoch base: g_rel persists across graph replays; all blocks read it before
    // anyone can advance it (release requires all 96 flags of gen start+1).
    const unsigned int start = g_rel;

    {
        const float4* wr = (const float4*)(W_hh + (size_t)gg * HD + hs0);
        #pragma unroll
        for (int q = 0; q < 8; q++) {
            float4 v = wr[q];
            sW[(q * 4 + 0) * 256 + tid] = v.x;
            sW[(q * 4 + 1) * 256 + tid] = v.y;
            sW[(q * 4 + 2) * 256 + tid] = v.z;
            sW[(q * 4 + 3) * 256 + tid] = v.w;
        }
    }
    sh[tid] = 0.f;
    sh[tid + 256] = 0.f;
    __syncthreads();

    for (int t = 0; t < TD; t++) {
        const int buf = t & 1;

        float acc[16];
        #pragma unroll
        for (int b = 0; b < 16; b++) acc[b] = 0.f;
        #pragma unroll
        for (int hrel = 0; hrel < 32; hrel++) {
            float w = sW[hrel * 256 + tid];
            const float4* hv = (const float4*)(sh + hrel * 16);
            float4 h0 = hv[0], h1 = hv[1], h2 = hv[2], h3 = hv[3];
            acc[0]  += w * h0.x; acc[1]  += w * h0.y; acc[2]  += w * h0.z; acc[3]  += w * h0.w;
            acc[4]  += w * h1.x; acc[5]  += w * h1.y; acc[6]  += w * h1.z; acc[7]  += w * h1.w;
            acc[8]  += w * h2.x; acc[9]  += w * h2.y; acc[10] += w * h2.z; acc[11] += w * h2.w;
            acc[12] += w * h3.x; acc[13] += w * h3.y; acc[14] += w * h3.z; acc[15] += w * h3.w;
        }
        {
            float* pbase = g_part + (size_t)(buf * 16 + ks) * (BB * G3);
            #pragma unroll
            for (int b = 0; b < 16; b++) pbase[(size_t)b * G3 + gg] = acc[b];
        }

        // ---- barrier ----
        __syncthreads();
        const unsigned int gen = start + (unsigned int)t + 1u;
        if (tid == 0) { __threadfence(); g_flags[blockIdx.x] = gen; }
        if (blockIdx.x == 0) {
            if (tid < 96) {
                while ((int)(g_flags[tid] - gen) < 0) { __nanosleep(32); }
            }
            __syncthreads();
            if (tid == 0) { __threadfence(); g_rel = gen; }
        }
        if (tid == 0) {
            while ((int)(g_rel - gen) < 0) { __nanosleep(32); }
            __threadfence();
        }
        __syncthreads();
        // ---- end barrier ----

        #pragma unroll
        for (int i = 0; i < 2; i++) {
            int p    = tid + i * 256;
            int b    = p >> 5;
            int jrel = p & 31;
            int j    = hs0 + jrel;
            float rs = 0.f, zs = 0.f, ns = 0.f;
            const float* pb = g_part + (size_t)buf * 16 * BB * G3 + (size_t)b * G3;
            #pragma unroll
            for (int k2 = 0; k2 < 16; k2++) {
                const float* pp = pb + (size_t)k2 * (BB * G3);
                rs += pp[j];
                zs += pp[512 + j];
                ns += pp[1024 + j];
            }
            rs += b_hh[j];
            zs += b_hh[512 + j];
            ns += b_hh[1024 + j];
            const float* xr = g_xp + ((size_t)b * TD + t) * G3;
            float r = 1.f / (1.f + expf(-(xr[j] + rs)));
            float z = 1.f / (1.f + expf(-(xr[512 + j] + zs)));
            float n = tanhf(xr[1024 + j] + r * ns);
            float hold = sh[jrel * 16 + b];
            float hnew = (1.f - z) * n + z * hold;
            bool  valid = (t < lengths[b]);
            float hkeep = valid ? hnew : hold;
            sh[jrel * 16 + b] = hkeep;
            if (gchunk == 0) {
                g_dec[((size_t)b * TD + t) * HD + j] = valid ? hnew : 0.f;
                if (t == TD - 1) g_hlast[(size_t)b * HD + j] = hkeep;
            }
        }
        __syncthreads();
    }
}

// ---------------- attention (unchanged, passing) ----------------
__global__ void attn_kernel(const float* __restrict__ encp,
                            const float* __restrict__ decp,
                            const float* __restrict__ enc,
                            const int*   __restrict__ dlen,
                            const int*   __restrict__ elen,
                            const float* __restrict__ b_attn,
                            const float* __restrict__ v_w,
                            float* __restrict__ context)
{
    const int bd = blockIdx.x;
    const int b  = bd >> 6;
    const int d  = bd & 63;
    const int tid = threadIdx.x;

    __shared__ float s_dp[HD];
    __shared__ float s_vw[HD];
    __shared__ float s_en[TE];
    __shared__ float s_mx, s_ssum;

    float* ctx_out = context + (size_t)bd * HD;
    const int Dl = dlen[b];
    const int El = elen[b];

    if (d >= Dl) {
        for (int i = tid; i < HD; i += 256) ctx_out[i] = 0.f;
        return;
    }

    for (int i = tid; i < HD; i += 256) {
        s_dp[i] = decp[(size_t)bd * HD + i] + b_attn[i];
        s_vw[i] = v_w[i];
    }
    __syncthreads();

    const int warp = tid >> 5, lane = tid & 31;
    for (int e = warp; e < El; e += 8) {
        const float* ep = encp + ((size_t)b * TE + e) * HD;
        float sum = 0.f;
        #pragma unroll 4
        for (int h = lane; h < HD; h += 32)
            sum += tanhf(ep[h] + s_dp[h]) * s_vw[h];
        #pragma unroll
        for (int off = 16; off; off >>= 1)
            sum += __shfl_xor_sync(0xffffffffu, sum, off);
        if (lane == 0) s_en[e] = sum;
    }
    __syncthreads();

    if (tid < 32) {
        float mx = -1e30f;
        for (int e = lane; e < El; e += 32) mx = fmaxf(mx, s_en[e]);
        #pragma unroll
        for (int off = 16; off; off >>= 1)
            mx = fmaxf(mx, __shfl_xor_sync(0xffffffffu, mx, off));
        float ss = 0.f;
        for (int e = lane; e < El; e += 32) ss += expf(s_en[e] - mx);
        #pragma unroll
        for (int off = 16; off; off >>= 1)
            ss += __shfl_xor_sync(0xffffffffu, ss, off);
        if (lane == 0) { s_mx = mx; s_ssum = ss; }
    }
    __syncthreads();
    if (tid < TE) s_en[tid] = (tid < El) ? expf(s_en[tid] - s_mx) / s_ssum : 0.f;
    __syncthreads();

    for (int h = tid; h < HD; h += 256) {
        float a = 0.f;
        for (int e = 0; e < El; e++)
            a += s_en[e] * enc[((size_t)b * TE + e) * HD + h];
        ctx_out[h] = a;
    }
}

__global__ void copy_hlast(float* __restrict__ out)
{
    out[blockIdx.x * HD + threadIdx.x] = g_hlast[blockIdx.x * HD + threadIdx.x];
}

// ---------------- fp32 -> fp16 converts ----------------
__global__ void conv_fp16(const float* __restrict__ src,
                          __half* __restrict__ dst, int n)
{
    int i = (blockIdx.x * 256 + threadIdx.x) * 8;
    if (i >= n) return;
    float4 v0 = *(const float4*)(src + i);
    float4 v1 = *(const float4*)(src + i + 4);
    __half2* dp = (__half2*)(dst + i);
    dp[0] = __floats2half2_rn(v0.x, v0.y);
    dp[1] = __floats2half2_rn(v0.z, v0.w);
    dp[2] = __floats2half2_rn(v1.x, v1.y);
    dp[3] = __floats2half2_rn(v1.z, v1.w);
}

// width-512 strided convert: row = i>>9, col = i&511
__global__ void conv512(const float* __restrict__ src, int srcStride,
                        __half* __restrict__ dst, int dstStride, int n)
{
    int i = (blockIdx.x * 256 + threadIdx.x) * 8;
    if (i >= n) return;
    int row = i >> 9, col = i & 511;
    const float* sp = src + (size_t)row * srcStride + col;
    float4 v0 = *(const float4*)sp;
    float4 v1 = *(const float4*)(sp + 4);
    __half2* dp = (__half2*)(dst + (size_t)row * dstStride + col);
    dp[0] = __floats2half2_rn(v0.x, v0.y);
    dp[1] = __floats2half2_rn(v0.z, v0.w);
    dp[2] = __floats2half2_rn(v1.x, v1.y);
    dp[3] = __floats2half2_rn(v1.z, v1.w);
}

// ---------------- generic fp16 wmma NT GEMM ----------------
// C[m,n] = sum_k A[m,k]*B[n,k] (+bias)(tanh), out fp32 or fp16.
// CTA tile 64x64, 4 warps (2x2 of 32x32), K chunks of 64, cp.async double buffer.
#define HF_TANH 1
#define HF_OUTH 2
#define HLDT 72
#define HARR (64 * HLDT)          // 4608 halves
#define HSTAGE (2 * HARR)         // 9216 halves = 18432 B
#define HSMEM (2 * HSTAGE * 2)    // 36864 B (epilogue 4*32*36*4 = 18432 fits)
#define HLDC 36

__device__ __forceinline__ void hload_stage(const __half* __restrict__ A, int lda,
                                            const __half* __restrict__ B, int ldb,
                                            int row0, int n0, int c,
                                            uint32_t smbase, int s, int tid)
{
    #pragma unroll
    for (int it = 0; it < 4; it++) {
        int i = tid + it * 128;         // 0..511 : 64 rows x 8 float4s
        int r = i >> 3, c4 = i & 7;
        const void* src = A + (size_t)(row0 + r) * lda + c * 64 + c4 * 8;
        cp16(smbase + (uint32_t)(s * HSTAGE) * 2u + (uint32_t)(r * (HLDT * 2) + c4 * 16), src);
    }
    #pragma unroll
    for (int it = 0; it < 4; it++) {
        int i = tid + it * 128;
        int r = i >> 3, c4 = i & 7;
        const void* src = B + (size_t)(n0 + r) * ldb + c * 64 + c4 * 8;
        cp16(smbase + (uint32_t)(s * HSTAGE + HARR) * 2u + (uint32_t)(r * (HLDT * 2) + c4 * 16), src);
    }
    asm volatile("cp.async.commit_group;" ::: "memory");
}

__global__ void __launch_bounds__(128, 2) hgemm_nt(
    const __half* __restrict__ A, int lda,
    const __half* __restrict__ B, int ldb,
    const float* __restrict__ bias,
    void* __restrict__ Cout, int ldc,
    int K, int flags)
{
    extern __shared__ __align__(16) char dsm[];
    __half* sm = (__half*)dsm;
    const uint32_t smbase = smem_u32(dsm);

    const int tid = threadIdx.x;
    const int wid = tid >> 5, lane = tid & 31;
    const int brow0 = blockIdx.y * 64;
    const int bn0   = blockIdx.x * 64;
    const int warp_m = wid >> 1, warp_n = wid & 1;
    const int nch = K / 64;

    wmma::fragment<wmma::accumulator, 16, 16, 16, float> acc[2][2];
    #pragma unroll
    for (int i = 0; i < 2; i++)
        #pragma unroll
        for (int j = 0; j < 2; j++)
            wmma::fill_fragment(acc[i][j], 0.f);

    hload_stage(A, lda, B, ldb, brow0, bn0, 0, smbase, 0, tid);
    hload_stage(A, lda, B, ldb, brow0, bn0, 1, smbase, 1, tid);

    for (int c = 0; c < nch; c++) {
        const int s = c & 1;
        if (c < nch - 1) asm volatile("cp.async.wait_group 1;" ::: "memory");
        else             asm volatile("cp.async.wait_group 0;" ::: "memory");
        __syncthreads();

        const __half* As = sm + s * HSTAGE;
        const __half* Bs = As + HARR;

        #pragma unroll
        for (int kk = 0; kk < 64; kk += 16) {
            wmma::fragment<wmma::matrix_a, 16, 16, 16, __half, wmma::row_major> a[2];
            wmma::fragment<wmma::matrix_b, 16, 16, 16, __half, wmma::col_major> b[2];
            #pragma unroll
            for (int i = 0; i < 2; i++)
                wmma::load_matrix_sync(a[i], As + (warp_m * 32 + i * 16) * HLDT + kk, HLDT);
            #pragma unroll
            for (int j = 0; j < 2; j++)
                wmma::load_matrix_sync(b[j], Bs + (warp_n * 32 + j * 16) * HLDT + kk, HLDT);
            #pragma unroll
            for (int i = 0; i < 2; i++)
                #pragma unroll
                for (int j = 0; j < 2; j++)
                    wmma::mma_sync(acc[i][j], a[i], b[j], acc[i][j]);
        }
        __syncthreads();

        if (c + 2 < nch) hload_stage(A, lda, B, ldb, brow0, bn0, c + 2, smbase, s, tid);
    }

    // epilogue: per-warp fp32 staging
    __syncthreads();
    float* ws = (float*)dsm + wid * 32 * HLDC;
    #pragma unroll
    for (int i = 0; i < 2; i++)
        #pragma unroll
        for (int j = 0; j < 2; j++)
            wmma::store_matrix_sync(ws + i * 16 * HLDC + j * 16, acc[i][j],
                                    HLDC, wmma::mem_row_major);
    __syncwarp();

    const int row0 = brow0 + warp_m * 32;
    const int n0   = bn0 + warp_n * 32;
    #pragma unroll
    for (int it = 0; it < 8; it++) {
        int idx = lane + it * 32;       // 0..255 : 32 rows x 8 float4s
        int r   = idx >> 3;
        int c4  = (idx & 7) * 4;
        float4 v = *(float4*)(ws + r * HLDC + c4);
        if (bias) {
            v.x += bias[n0 + c4 + 0];
            v.y += bias[n0 + c4 + 1];
            v.z += bias[n0 + c4 + 2];
            v.w += bias[n0 + c4 + 3];
        }
        if (flags & HF_TANH) {
            v.x = tanhf(v.x); v.y = tanhf(v.y); v.z = tanhf(v.z); v.w = tanhf(v.w);
        }
        if (flags & HF_OUTH) {
            __half* cp = (__half*)Cout + (size_t)(row0 + r) * ldc + n0 + c4;
            *(__half2*)(cp)     = __floats2half2_rn(v.x, v.y);
            *(__half2*)(cp + 2) = __floats2half2_rn(v.z, v.w);
        } else {
            *(float4*)((float*)Cout + (size_t)(row0 + r) * ldc + n0 + c4) = v;
        }
    }
}

// ---------------- wmma logits GEMM (unchanged from round 9) ----------------
#define LBK   32
#define LDT   40
#define ARR_ELEMS (128 * LDT)
#define STAGE_ELEMS (2 * ARR_ELEMS)
#define LDC_W 68
#define SMEM_LOGITS (4 * 64 * LDC_W * 4)  // 69632

__device__ __forceinline__ void load_stage_logits(int tid, int mt, int nt, int c,
                                                  uint32_t smbase, int s)
{
    const __half* srcs[2] = {
        g_Ah + (size_t)mt * 128 * HD,
        g_Bh + (size_t)nt * 128 * HD
    };
    #pragma unroll
    for (int arr = 0; arr < 2; arr++) {
        #pragma unroll
        for (int it = 0; it < 4; it++) {
            int i  = tid + it * 128;
            int r  = i >> 2;
            int c4 = i & 3;
            const void* src = srcs[arr] + (size_t)r * HD + c * LBK + c4 * 8;
            uint32_t dst = smbase + (uint32_t)(s * STAGE_ELEMS + arr * ARR_ELEMS) * 2u
                         + (uint32_t)(r * (LDT * 2) + c4 * 16);
            cp16(dst, src);
        }
    }
    asm volatile("cp.async.commit_group;" ::: "memory");
}

__global__ void __launch_bounds__(128, 2) logits_wmma(const float* __restrict__ b_out,
                                                      float* __restrict__ out)
{
    extern __shared__ __align__(16) char dynsmem[];
    __half* sm = (__half*)dynsmem;
    const uint32_t smbase = smem_u32(dynsmem);

    const int tid = threadIdx.x;
    const int wid = tid >> 5, lane = tid & 31;
    const int nt = blockIdx.x;
    const int mt = blockIdx.y;
    const int warp_m = wid >> 1;
    const int warp_n = wid & 1;

    wmma::fragment<wmma::accumulator, 16, 16, 16, float> acc[4][4];
    #pragma unroll
    for (int i = 0; i < 4; i++)
        #pragma unroll
        for (int j = 0; j < 4; j++)
            wmma::fill_fragment(acc[i][j], 0.f);

    load_stage_logits(tid, mt, nt, 0, smbase, 0);
    load_stage_logits(tid, mt, nt, 1, smbase, 1);

    for (int c = 0; c < 16; c++) {
        const int s = c & 1;
        if (c < 15) asm volatile("cp.async.wait_group 1;" ::: "memory");
        else        asm volatile("cp.async.wait_group 0;" ::: "memory");
        __syncthreads();

        const __half* As = sm + s * STAGE_ELEMS;
        const __half* Bs = As + ARR_ELEMS;

        #pragma unroll
        for (int kk = 0; kk < LBK; kk += 16) {
            wmma::fragment<wmma::matrix_a, 16, 16, 16, __half, wmma::row_major> a[4];
            wmma::fragment<wmma::matrix_b, 16, 16, 16, __half, wmma::col_major> b[4];
            #pragma unroll
            for (int i = 0; i < 4; i++)
                wmma::load_matrix_sync(a[i], As + (warp_m * 64 + i * 16) * LDT + kk, LDT);
            #pragma unroll
            for (int j = 0; j < 4; j++)
                wmma::load_matrix_sync(b[j], Bs + (warp_n * 64 + j * 16) * LDT + kk, LDT);
            #pragma unroll
            for (int i = 0; i < 4; i++)
                #pragma unroll
                for (int j = 0; j < 4; j++)
                    wmma::mma_sync(acc[i][j], a[i], b[j], acc[i][j]);
        }
        __syncthreads();

        if (c + 2 < 16) load_stage_logits(tid, mt, nt, c + 2, smbase, s);
    }

    __syncthreads();
    float* ws = (float*)dynsmem + wid * 64 * LDC_W;
    #pragma unroll
    for (int i = 0; i < 4; i++)
        #pragma unroll
        for (int j = 0; j < 4; j++)
            wmma::store_matrix_sync(ws + i * 16 * LDC_W + j * 16, acc[i][j],
                                    LDC_W, wmma::mem_row_major);
    __syncwarp();

    const int row0 = mt * 128 + warp_m * 64;
    const int n0   = nt * 128 + warp_n * 64;
    #pragma unroll
    for (int it = 0; it < 32; it++) {
        int idx = lane + it * 32;
        int r   = idx >> 4;
        int c4  = (idx & 15) * 4;
        float4 v = *(float4*)(ws + r * LDC_W + c4);
        v.x += b_out[n0 + c4 + 0];
        v.y += b_out[n0 + c4 + 1];
        v.z += b_out[n0 + c4 + 2];
        v.w += b_out[n0 + c4 + 3];
        *(float4*)(out + (size_t)(row0 + r) * VV + n0 + c4) = v;
    }
}

// ---------------- launch ----------------
extern "C" void kernel_launch(void* const* d_in, const int* in_sizes, int n_in,
                              void* d_out, int out_size)
{
    const float* x      = (const float*)d_in[0];
    const int*   inlen  = (const int*)  d_in[1];
    const float* enc    = (const float*)d_in[2];
    const int*   enclen = (const int*)  d_in[3];
    const float* W_ih   = (const float*)d_in[4];
    const float* W_hh   = (const float*)d_in[5];
    const float* b_ih   = (const float*)d_in[6];
    const float* W_attn = (const float*)d_in[8];
    const float* b_attn = (const float*)d_in[9];
    const float* v_w    = (const float*)d_in[10];
    const float* W_dense= (const float*)d_in[12];
    const float* b_dense= (const float*)d_in[13];
    const float* W_out  = (const float*)d_in[14];
    const float* b_out  = (const float*)d_in[15];
    const float* b_hh   = (const float*)d_in[7];

    float* out = (float*)d_out;

    float* xp    = nullptr; cudaGetSymbolAddress((void**)&xp,    g_xp);
    float* dec   = nullptr; cudaGetSymbolAddress((void**)&dec,   g_dec);
    float* encp  = nullptr; cudaGetSymbolAddress((void**)&encp,  g_encp);
    float* decp  = nullptr; cudaGetSymbolAddress((void**)&decp,  g_decp);
    float* ctx   = nullptr; cudaGetSymbolAddress((void**)&ctx,   g_ctx);
    __half* Ah   = nullptr; cudaGetSymbolAddress((void**)&Ah,   g_Ah);
    __half* Bh   = nullptr; cudaGetSymbolAddress((void**)&Bh,   g_Bh);
    __half* ench = nullptr; cudaGetSymbolAddress((void**)&ench, g_ench);
    __half* cat  = nullptr; cudaGetSymbolAddress((void**)&cat,  g_cat);
    __half* Wae  = nullptr; cudaGetSymbolAddress((void**)&Wae,  g_Wae);
    __half* Wad  = nullptr; cudaGetSymbolAddress((void**)&Wad,  g_Wad);
    __half* Wdh  = nullptr; cudaGetSymbolAddress((void**)&Wdh,  g_Wdh);

    cudaFuncSetAttribute(logits_wmma, cudaFuncAttributeMaxDynamicSharedMemorySize, SMEM_LOGITS);

    // 1) x_proj (fp32 — feeds GRU recurrence & h_last, keep exact-ish)
    sgemm_nt<<<dim3(G3 / 64, (BB * TD) / 64), 256>>>(x, HD, W_ih, HD, b_ih, xp, G3, HD);

    // weight converts (input-only, independent)
    conv_fp16<<<((size_t)VV * HD) / 2048, 256>>>(W_out, Bh, VV * HD);
    conv_fp16<<<(HD * 2 * HD) / 2048, 256>>>(W_dense, Wdh, HD * 2 * HD);
    conv512<<<(HD * HD) / 2048, 256>>>(W_attn,      2 * HD, Wae, HD, HD * HD);
    conv512<<<(HD * HD) / 2048, 256>>>(W_attn + HD, 2 * HD, Wad, HD, HD * HD);
    conv512<<<(BB * TE * HD) / 2048, 256>>>(enc, HD, ench, HD, BB * TE * HD);

    // 2) GRU scan
    gru_scan<<<96, 256>>>(W_hh, b_hh, inlen);

    // dec -> cat[:, 0:512]
    conv512<<<(BB * TD * HD) / 2048, 256>>>(dec, HD, cat, 2 * HD, BB * TD * HD);

    // 3,4) attention projections (fp16 wmma, fp32 out)
    hgemm_nt<<<dim3(HD / 64, (BB * TE) / 64), 128, HSMEM>>>(ench, HD, Wae, HD, nullptr, encp, HD, HD, 0);
    hgemm_nt<<<dim3(HD / 64, (BB * TD) / 64), 128, HSMEM>>>(cat, 2 * HD, Wad, HD, nullptr, decp, HD, HD, 0);

    // 5) attention
    attn_kernel<<<BB * TD, 256>>>(encp, decp, enc, inlen, enclen, b_attn, v_w, ctx);

    // ctx -> cat[:, 512:1024]
    conv512<<<(BB * TD * HD) / 2048, 256>>>(ctx, HD, cat + HD, 2 * HD, BB * TD * HD);

    // 6,7) dense = tanh(cat @ W_dense^T + b) -> fp16 Ah directly
    hgemm_nt<<<dim3(HD / 64, (BB * TD) / 64), 128, HSMEM>>>(cat, 2 * HD, Wdh, 2 * HD, b_dense, Ah, HD,
                                                            2 * HD, HF_TANH | HF_OUTH);

    // 8) logits
    logits_wmma<<<dim3(VV / 128, (BB * TD) / 128), 128, SMEM_LOGITS>>>(b_out, out);

    // 9) h_last tail
    copy_hlast<<<BB, HD>>>(out + LOGITS_ELEMS);
}

// round 11
// speedup vs baseline: 2.3776x; 1.0355x over previous
#include <cuda_runtime.h>
#include <cuda_fp16.h>
#include <mma.h>
#include <math.h>
#include <stdint.h>

using namespace nvcuda;

// Problem constants
#define BB   16
#define TD   64
#define TE   64
#define HD   512
#define G3   1536
#define VV   32000
#define LOGITS_ELEMS (BB*TD*VV)   // 32768000

// ---------------- scratch (__device__ globals, no allocation) ----------------
__device__ float g_xp   [BB*TD*G3];
__device__ float g_part [2*16*BB*G3];
__device__ float g_encp [BB*TE*HD];
__device__ float g_decp [BB*TD*HD];
__device__ float g_hlast[BB*HD];

// fp16 operands
__device__ __half g_Ah  [BB*TD*HD];          // dense output (tanh), feeds logits
__device__ __half g_Bh  [(size_t)VV*HD];     // W_out
__device__ __half g_ench[BB*TE*HD];          // enc
__device__ __half g_cat [BB*TD*2*HD];        // [dec | ctx] fp16 (written by gru & attn)
__device__ __half g_Wae [HD*HD];             // W_attn[:, :512]
__device__ __half g_Wad [HD*HD];             // W_attn[:, 512:]
__device__ __half g_Wdh [HD*2*HD];           // W_dense
__device__ __half g_xh  [BB*TD*HD];          // x fp16
__device__ __half g_Wih [G3*HD];             // W_ih fp16

// barrier state (persists across graph replays; epoch-based)
__device__ volatile unsigned int g_flags[96];
__device__ volatile unsigned int g_rel;

// ---------------- helpers (baseline-PTX only) ----------------
__device__ __forceinline__ uint32_t smem_u32(const void* p) {
    uint32_t a;
    asm("{ .reg .u64 t; cvta.to.shared.u64 t, %1; cvt.u32.u64 %0, t; }" : "=r"(a) : "l"(p));
    return a;
}
__device__ __forceinline__ void cp16(uint32_t s, const void* g) {
    asm volatile("cp.async.cg.shared.global [%0], [%1], 16;" :: "r"(s), "l"(g));
}

// ---------------- persistent GRU scan (all-to-all flag barrier) ----------------
__global__ void gru_scan(const float* __restrict__ W_hh,
                         const float* __restrict__ b_hh,
                         const int*   __restrict__ lengths)
{
    __shared__ float sW[32 * 256];
    __shared__ float sh[32 * 16];

    const int tid    = threadIdx.x;
    const int gchunk = blockIdx.x / 16;
    const int ks     = blockIdx.x % 16;
    const int g0     = gchunk * 256;
    const int hs0    = ks * 32;
    const int gg     = g0 + tid;

    const unsigned int start = g_rel;   // all blocks read before any flag of this epoch

    {
        const float4* wr = (const float4*)(W_hh + (size_t)gg * HD + hs0);
        #pragma unroll
        for (int q = 0; q < 8; q++) {
            float4 v = wr[q];
            sW[(q * 4 + 0) * 256 + tid] = v.x;
            sW[(q * 4 + 1) * 256 + tid] = v.y;
            sW[(q * 4 + 2) * 256 + tid] = v.z;
            sW[(q * 4 + 3) * 256 + tid] = v.w;
        }
    }
    sh[tid] = 0.f;
    sh[tid + 256] = 0.f;
    __syncthreads();

    for (int t = 0; t < TD; t++) {
        const int buf = t & 1;

        float acc[16];
        #pragma unroll
        for (int b = 0; b < 16; b++) acc[b] = 0.f;
        #pragma unroll
        for (int hrel = 0; hrel < 32; hrel++) {
            float w = sW[hrel * 256 + tid];
            const float4* hv = (const float4*)(sh + hrel * 16);
            float4 h0 = hv[0], h1 = hv[1], h2 = hv[2], h3 = hv[3];
            acc[0]  += w * h0.x; acc[1]  += w * h0.y; acc[2]  += w * h0.z; acc[3]  += w * h0.w;
            acc[4]  += w * h1.x; acc[5]  += w * h1.y; acc[6]  += w * h1.z; acc[7]  += w * h1.w;
            acc[8]  += w * h2.x; acc[9]  += w * h2.y; acc[10] += w * h2.z; acc[11] += w * h2.w;
            acc[12] += w * h3.x; acc[13] += w * h3.y; acc[14] += w * h3.z; acc[15] += w * h3.w;
        }
        {
            float* pbase = g_part + (size_t)(buf * 16 + ks) * (BB * G3);
            #pragma unroll
            for (int b = 0; b < 16; b++) pbase[(size_t)b * G3 + gg] = acc[b];
        }

        // ---- all-to-all barrier: one store, every block polls all 96 flags ----
        __syncthreads();
        const unsigned int gen = start + (unsigned int)t + 1u;
        if (tid == 0) { __threadfence(); g_flags[blockIdx.x] = gen; }
        if (tid < 96) {
            while ((int)(g_flags[tid] - gen) < 0) { __nanosleep(20); }
            __threadfence();
        }
        __syncthreads();
        // ---- end barrier ----

        #pragma unroll
        for (int i = 0; i < 2; i++) {
            int p    = tid + i * 256;
            int b    = p >> 5;
            int jrel = p & 31;
            int j    = hs0 + jrel;
            float rs = 0.f, zs = 0.f, ns = 0.f;
            const float* pb = g_part + (size_t)buf * 16 * BB * G3 + (size_t)b * G3;
            #pragma unroll
            for (int k2 = 0; k2 < 16; k2++) {
                const float* pp = pb + (size_t)k2 * (BB * G3);
                rs += pp[j];
                zs += pp[512 + j];
                ns += pp[1024 + j];
            }
            rs += b_hh[j];
            zs += b_hh[512 + j];
            ns += b_hh[1024 + j];
            const float* xr = g_xp + ((size_t)b * TD + t) * G3;
            float r = 1.f / (1.f + expf(-(xr[j] + rs)));
            float z = 1.f / (1.f + expf(-(xr[512 + j] + zs)));
            float n = tanhf(xr[1024 + j] + r * ns);
            float hold = sh[jrel * 16 + b];
            float hnew = (1.f - z) * n + z * hold;
            bool  valid = (t < lengths[b]);
            float hkeep = valid ? hnew : hold;
            sh[jrel * 16 + b] = hkeep;
            if (gchunk == 0) {
                g_cat[((size_t)b * TD + t) * (2 * HD) + j] = __float2half(valid ? hnew : 0.f);
                if (t == TD - 1) g_hlast[(size_t)b * HD + j] = hkeep;
            }
        }
        __syncthreads();
    }

    // advance epoch for next replay (all flags already at start+TD)
    if (blockIdx.x == 0 && tid == 0) g_rel = start + (unsigned int)TD;
}

// ---------------- attention: writes fp16 ctx directly into g_cat ----------------
__global__ void attn_kernel(const float* __restrict__ encp,
                            const float* __restrict__ decp,
                            const float* __restrict__ enc,
                            const int*   __restrict__ dlen,
                            const int*   __restrict__ elen,
                            const float* __restrict__ b_attn,
                            const float* __restrict__ v_w,
                            __half* __restrict__ cat)
{
    const int bd = blockIdx.x;
    const int b  = bd >> 6;
    const int d  = bd & 63;
    const int tid = threadIdx.x;

    __shared__ float s_dp[HD];
    __shared__ float s_vw[HD];
    __shared__ float s_en[TE];
    __shared__ float s_mx, s_ssum;

    __half* ctx_out = cat + (size_t)bd * (2 * HD) + HD;
    const int Dl = dlen[b];
    const int El = elen[b];

    if (d >= Dl) {
        for (int i = tid; i < HD; i += 256) ctx_out[i] = __float2half(0.f);
        return;
    }

    for (int i = tid; i < HD; i += 256) {
        s_dp[i] = decp[(size_t)bd * HD + i] + b_attn[i];
        s_vw[i] = v_w[i];
    }
    __syncthreads();

    const int warp = tid >> 5, lane = tid & 31;
    for (int e = warp; e < El; e += 8) {
        const float* ep = encp + ((size_t)b * TE + e) * HD;
        float sum = 0.f;
        #pragma unroll 4
        for (int h = lane; h < HD; h += 32)
            sum += tanhf(ep[h] + s_dp[h]) * s_vw[h];
        #pragma unroll
        for (int off = 16; off; off >>= 1)
            sum += __shfl_xor_sync(0xffffffffu, sum, off);
        if (lane == 0) s_en[e] = sum;
    }
    __syncthreads();

    if (tid < 32) {
        float mx = -1e30f;
        for (int e = lane; e < El; e += 32) mx = fmaxf(mx, s_en[e]);
        #pragma unroll
        for (int off = 16; off; off >>= 1)
            mx = fmaxf(mx, __shfl_xor_sync(0xffffffffu, mx, off));
        float ss = 0.f;
        for (int e = lane; e < El; e += 32) ss += expf(s_en[e] - mx);
        #pragma unroll
        for (int off = 16; off; off >>= 1)
            ss += __shfl_xor_sync(0xffffffffu, ss, off);
        if (lane == 0) { s_mx = mx; s_ssum = ss; }
    }
    __syncthreads();
    if (tid < TE) s_en[tid] = (tid < El) ? expf(s_en[tid] - s_mx) / s_ssum : 0.f;
    __syncthreads();

    for (int h = tid; h < HD; h += 256) {
        float a = 0.f;
        for (int e = 0; e < El; e++)
            a += s_en[e] * enc[((size_t)b * TE + e) * HD + h];
        ctx_out[h] = __float2half(a);
    }
}

__global__ void copy_hlast(float* __restrict__ out)
{
    out[blockIdx.x * HD + threadIdx.x] = g_hlast[blockIdx.x * HD + threadIdx.x];
}

// ---------------- fp32 -> fp16 converts ----------------
__global__ void conv_fp16(const float* __restrict__ src,
                          __half* __restrict__ dst, int n)
{
    int i = (blockIdx.x * 256 + threadIdx.x) * 8;
    if (i >= n) return;
    float4 v0 = *(const float4*)(src + i);
    float4 v1 = *(const float4*)(src + i + 4);
    __half2* dp = (__half2*)(dst + i);
    dp[0] = __floats2half2_rn(v0.x, v0.y);
    dp[1] = __floats2half2_rn(v0.z, v0.w);
    dp[2] = __floats2half2_rn(v1.x, v1.y);
    dp[3] = __floats2half2_rn(v1.z, v1.w);
}

// width-512 strided convert: row = i>>9, col = i&511
__global__ void conv512(const float* __restrict__ src, int srcStride,
                        __half* __restrict__ dst, int dstStride, int n)
{
    int i = (blockIdx.x * 256 + threadIdx.x) * 8;
    if (i >= n) return;
    int row = i >> 9, col = i & 511;
    const float* sp = src + (size_t)row * srcStride + col;
    float4 v0 = *(const float4*)sp;
    float4 v1 = *(const float4*)(sp + 4);
    __half2* dp = (__half2*)(dst + (size_t)row * dstStride + col);
    dp[0] = __floats2half2_rn(v0.x, v0.y);
    dp[1] = __floats2half2_rn(v0.z, v0.w);
    dp[2] = __floats2half2_rn(v1.x, v1.y);
    dp[3] = __floats2half2_rn(v1.z, v1.w);
}

// ---------------- generic fp16 wmma NT GEMM ----------------
#define HF_TANH 1
#define HF_OUTH 2
#define HLDT 72
#define HARR (64 * HLDT)
#define HSTAGE (2 * HARR)
#define HSMEM (2 * HSTAGE * 2)    // 36864 B
#define HLDC 36

__device__ __forceinline__ void hload_stage(const __half* __restrict__ A, int lda,
                                            const __half* __restrict__ B, int ldb,
                                            int row0, int n0, int c,
                                            uint32_t smbase, int s, int tid)
{
    #pragma unroll
    for (int it = 0; it < 4; it++) {
        int i = tid + it * 128;
        int r = i >> 3, c4 = i & 7;
        const void* src = A + (size_t)(row0 + r) * lda + c * 64 + c4 * 8;
        cp16(smbase + (uint32_t)(s * HSTAGE) * 2u + (uint32_t)(r * (HLDT * 2) + c4 * 16), src);
    }
    #pragma unroll
    for (int it = 0; it < 4; it++) {
        int i = tid + it * 128;
        int r = i >> 3, c4 = i & 7;
        const void* src = B + (size_t)(n0 + r) * ldb + c * 64 + c4 * 8;
        cp16(smbase + (uint32_t)(s * HSTAGE + HARR) * 2u + (uint32_t)(r * (HLDT * 2) + c4 * 16), src);
    }
    asm volatile("cp.async.commit_group;" ::: "memory");
}

__global__ void __launch_bounds__(128, 2) hgemm_nt(
    const __half* __restrict__ A, int lda,
    const __half* __restrict__ B, int ldb,
    const float* __restrict__ bias,
    void* __restrict__ Cout, int ldc,
    int K, int flags)
{
    extern __shared__ __align__(16) char dsm[];
    __half* sm = (__half*)dsm;
    const uint32_t smbase = smem_u32(dsm);

    const int tid = threadIdx.x;
    const int wid = tid >> 5, lane = tid & 31;
    const int brow0 = blockIdx.y * 64;
    const int bn0   = blockIdx.x * 64;
    const int warp_m = wid >> 1, warp_n = wid & 1;
    const int nch = K / 64;

    wmma::fragment<wmma::accumulator, 16, 16, 16, float> acc[2][2];
    #pragma unroll
    for (int i = 0; i < 2; i++)
        #pragma unroll
        for (int j = 0; j < 2; j++)
            wmma::fill_fragment(acc[i][j], 0.f);

    hload_stage(A, lda, B, ldb, brow0, bn0, 0, smbase, 0, tid);
    hload_stage(A, lda, B, ldb, brow0, bn0, 1, smbase, 1, tid);

    for (int c = 0; c < nch; c++) {
        const int s = c & 1;
        if (c < nch - 1) asm volatile("cp.async.wait_group 1;" ::: "memory");
        else             asm volatile("cp.async.wait_group 0;" ::: "memory");
        __syncthreads();

        const __half* As = sm + s * HSTAGE;
        const __half* Bs = As + HARR;

        #pragma unroll
        for (int kk = 0; kk < 64; kk += 16) {
            wmma::fragment<wmma::matrix_a, 16, 16, 16, __half, wmma::row_major> a[2];
            wmma::fragment<wmma::matrix_b, 16, 16, 16, __half, wmma::col_major> b[2];
            #pragma unroll
            for (int i = 0; i < 2; i++)
                wmma::load_matrix_sync(a[i], As + (warp_m * 32 + i * 16) * HLDT + kk, HLDT);
            #pragma unroll
            for (int j = 0; j < 2; j++)
                wmma::load_matrix_sync(b[j], Bs + (warp_n * 32 + j * 16) * HLDT + kk, HLDT);
            #pragma unroll
            for (int i = 0; i < 2; i++)
                #pragma unroll
                for (int j = 0; j < 2; j++)
                    wmma::mma_sync(acc[i][j], a[i], b[j], acc[i][j]);
        }
        __syncthreads();

        if (c + 2 < nch) hload_stage(A, lda, B, ldb, brow0, bn0, c + 2, smbase, s, tid);
    }

    __syncthreads();
    float* ws = (float*)dsm + wid * 32 * HLDC;
    #pragma unroll
    for (int i = 0; i < 2; i++)
        #pragma unroll
        for (int j = 0; j < 2; j++)
            wmma::store_matrix_sync(ws + i * 16 * HLDC + j * 16, acc[i][j],
                                    HLDC, wmma::mem_row_major);
    __syncwarp();

    const int row0 = brow0 + warp_m * 32;
    const int n0   = bn0 + warp_n * 32;
    #pragma unroll
    for (int it = 0; it < 8; it++) {
        int idx = lane + it * 32;
        int r   = idx >> 3;
        int c4  = (idx & 7) * 4;
        float4 v = *(float4*)(ws + r * HLDC + c4);
        if (bias) {
            v.x += bias[n0 + c4 + 0];
            v.y += bias[n0 + c4 + 1];
            v.z += bias[n0 + c4 + 2];
            v.w += bias[n0 + c4 + 3];
        }
        if (flags & HF_TANH) {
            v.x = tanhf(v.x); v.y = tanhf(v.y); v.z = tanhf(v.z); v.w = tanhf(v.w);
        }
        if (flags & HF_OUTH) {
            __half* cp = (__half*)Cout + (size_t)(row0 + r) * ldc + n0 + c4;
            *(__half2*)(cp)     = __floats2half2_rn(v.x, v.y);
            *(__half2*)(cp + 2) = __floats2half2_rn(v.z, v.w);
        } else {
            *(float4*)((float*)Cout + (size_t)(row0 + r) * ldc + n0 + c4) = v;
        }
    }
}

// ---------------- wmma logits GEMM (LBK 64) ----------------
#define LBK   64
#define LDT   72
#define ARR_ELEMS (128 * LDT)             // 9216 halves
#define STAGE_ELEMS (2 * ARR_ELEMS)       // 18432 halves = 36864 B
#define LDC_W 68
#define SMEM_LOGITS 73728                 // 2 stages; epilogue 69632 fits

__device__ __forceinline__ void load_stage_logits(int tid, int mt, int nt, int c,
                                                  uint32_t smbase, int s)
{
    const __half* srcs[2] = {
        g_Ah + (size_t)mt * 128 * HD,
        g_Bh + (size_t)nt * 128 * HD
    };
    #pragma unroll
    for (int arr = 0; arr < 2; arr++) {
        #pragma unroll
        for (int it = 0; it < 8; it++) {
            int i  = tid + it * 128;       // 0..1023 : 128 rows x 8 granules
            int r  = i >> 3;
            int g  = i & 7;
            const void* src = srcs[arr] + (size_t)r * HD + c * LBK + g * 8;
            uint32_t dst = smbase + (uint32_t)(s * STAGE_ELEMS + arr * ARR_ELEMS) * 2u
                         + (uint32_t)(r * (LDT * 2) + g * 16);
            cp16(dst, src);
        }
    }
    asm volatile("cp.async.commit_group;" ::: "memory");
}

__global__ void __launch_bounds__(128, 2) logits_wmma(const float* __restrict__ b_out,
                                                      float* __restrict__ out)
{
    extern __shared__ __align__(16) char dynsmem[];
    __half* sm = (__half*)dynsmem;
    const uint32_t smbase = smem_u32(dynsmem);

    const int tid = threadIdx.x;
    const int wid = tid >> 5, lane = tid & 31;
    const int nt = blockIdx.x;
    const int mt = blockIdx.y;
    const int warp_m = wid >> 1;
    const int warp_n = wid & 1;

    wmma::fragment<wmma::accumulator, 16, 16, 16, float> acc[4][4];
    #pragma unroll
    for (int i = 0; i < 4; i++)
        #pragma unroll
        for (int j = 0; j < 4; j++)
            wmma::fill_fragment(acc[i][j], 0.f);

    load_stage_logits(tid, mt, nt, 0, smbase, 0);
    load_stage_logits(tid, mt, nt, 1, smbase, 1);

    for (int c = 0; c < 8; c++) {
        const int s = c & 1;
        if (c < 7) asm volatile("cp.async.wait_group 1;" ::: "memory");
        else       asm volatile("cp.async.wait_group 0;" ::: "memory");
        __syncthreads();

        const __half* As = sm + s * STAGE_ELEMS;
        const __half* Bs = As + ARR_ELEMS;

        #pragma unroll
        for (int kk = 0; kk < LBK; kk += 16) {
            wmma::fragment<wmma::matrix_a, 16, 16, 16, __half, wmma::row_major> a[4];
            wmma::fragment<wmma::matrix_b, 16, 16, 16, __half, wmma::col_major> b[4];
            #pragma unroll
            for (int i = 0; i < 4; i++)
                wmma::load_matrix_sync(a[i], As + (warp_m * 64 + i * 16) * LDT + kk, LDT);
            #pragma unroll
            for (int j = 0; j < 4; j++)
                wmma::load_matrix_sync(b[j], Bs + (warp_n * 64 + j * 16) * LDT + kk, LDT);
            #pragma unroll
            for (int i = 0; i < 4; i++)
                #pragma unroll
                for (int j = 0; j < 4; j++)
                    wmma::mma_sync(acc[i][j], a[i], b[j], acc[i][j]);
        }
        __syncthreads();

        if (c + 2 < 8) load_stage_logits(tid, mt, nt, c + 2, smbase, s);
    }

    __syncthreads();
    float* ws = (float*)dynsmem + wid * 64 * LDC_W;
    #pragma unroll
    for (int i = 0; i < 4; i++)
        #pragma unroll
        for (int j = 0; j < 4; j++)
            wmma::store_matrix_sync(ws + i * 16 * LDC_W + j * 16, acc[i][j],
                                    LDC_W, wmma::mem_row_major);
    __syncwarp();

    const int row0 = mt * 128 + warp_m * 64;
    const int n0   = nt * 128 + warp_n * 64;
    #pragma unroll
    for (int it = 0; it < 32; it++) {
        int idx = lane + it * 32;
        int r   = idx >> 4;
        int c4  = (idx & 15) * 4;
        float4 v = *(float4*)(ws + r * LDC_W + c4);
        v.x += b_out[n0 + c4 + 0];
        v.y += b_out[n0 + c4 + 1];
        v.z += b_out[n0 + c4 + 2];
        v.w += b_out[n0 + c4 + 3];
        *(float4*)(out + (size_t)(row0 + r) * VV + n0 + c4) = v;
    }
}

// ---------------- launch ----------------
extern "C" void kernel_launch(void* const* d_in, const int* in_sizes, int n_in,
                              void* d_out, int out_size)
{
    const float* x      = (const float*)d_in[0];
    const int*   inlen  = (const int*)  d_in[1];
    const float* enc    = (const float*)d_in[2];
    const int*   enclen = (const int*)  d_in[3];
    const float* W_ih   = (const float*)d_in[4];
    const float* W_hh   = (const float*)d_in[5];
    const float* b_ih   = (const float*)d_in[6];
    const float* b_hh   = (const float*)d_in[7];
    const float* W_attn = (const float*)d_in[8];
    const float* b_attn = (const float*)d_in[9];
    const float* v_w    = (const float*)d_in[10];
    const float* W_dense= (const float*)d_in[12];
    const float* b_dense= (const float*)d_in[13];
    const float* W_out  = (const float*)d_in[14];
    const float* b_out  = (const float*)d_in[15];

    float* out = (float*)d_out;

    float* xp    = nullptr; cudaGetSymbolAddress((void**)&xp,    g_xp);
    float* encp  = nullptr; cudaGetSymbolAddress((void**)&encp,  g_encp);
    float* decp  = nullptr; cudaGetSymbolAddress((void**)&decp,  g_decp);
    __half* Ah   = nullptr; cudaGetSymbolAddress((void**)&Ah,   g_Ah);
    __half* Bh   = nullptr; cudaGetSymbolAddress((void**)&Bh,   g_Bh);
    __half* ench = nullptr; cudaGetSymbolAddress((void**)&ench, g_ench);
    __half* cat  = nullptr; cudaGetSymbolAddress((void**)&cat,  g_cat);
    __half* Wae  = nullptr; cudaGetSymbolAddress((void**)&Wae,  g_Wae);
    __half* Wad  = nullptr; cudaGetSymbolAddress((void**)&Wad,  g_Wad);
    __half* Wdh  = nullptr; cudaGetSymbolAddress((void**)&Wdh,  g_Wdh);
    __half* xh   = nullptr; cudaGetSymbolAddress((void**)&xh,   g_xh);
    __half* Wih  = nullptr; cudaGetSymbolAddress((void**)&Wih,  g_Wih);

    cudaFuncSetAttribute(logits_wmma, cudaFuncAttributeMaxDynamicSharedMemorySize, SMEM_LOGITS);

    // input-only converts
    conv_fp16<<<((size_t)VV * HD) / 2048, 256>>>(W_out, Bh, VV * HD);
    conv_fp16<<<(HD * 2 * HD) / 2048, 256>>>(W_dense, Wdh, HD * 2 * HD);
    conv512<<<(HD * HD) / 2048, 256>>>(W_attn,      2 * HD, Wae, HD, HD * HD);
    conv512<<<(HD * HD) / 2048, 256>>>(W_attn + HD, 2 * HD, Wad, HD, HD * HD);
    conv512<<<(BB * TE * HD) / 2048, 256>>>(enc, HD, ench, HD, BB * TE * HD);
    conv_fp16<<<(BB * TD * HD) / 2048, 256>>>(x, xh, BB * TD * HD);
    conv_fp16<<<(G3 * HD) / 2048, 256>>>(W_ih, Wih, G3 * HD);

    // 1) x_proj via fp16 wmma (fp32 out)
    hgemm_nt<<<dim3(G3 / 64, (BB * TD) / 64), 128, HSMEM>>>(xh, HD, Wih, HD, b_ih, xp, G3, HD, 0);

    // 2) GRU scan (writes fp16 dec into g_cat[:, :512] + g_hlast)
    gru_scan<<<96, 256>>>(W_hh, b_hh, inlen);

    // 3,4) attention projections
    hgemm_nt<<<dim3(HD / 64, (BB * TE) / 64), 128, HSMEM>>>(ench, HD, Wae, HD, nullptr, encp, HD, HD, 0);
    hgemm_nt<<<dim3(HD / 64, (BB * TD) / 64), 128, HSMEM>>>(cat, 2 * HD, Wad, HD, nullptr, decp, HD, HD, 0);

    // 5) attention (writes fp16 ctx into g_cat[:, 512:])
    attn_kernel<<<BB * TD, 256>>>(encp, decp, enc, inlen, enclen, b_attn, v_w, cat);

    // 6,7) dense = tanh(cat @ W_dense^T + b) -> fp16 Ah
    hgemm_nt<<<dim3(HD / 64, (BB * TD) / 64), 128, HSMEM>>>(cat, 2 * HD, Wdh, 2 * HD, b_dense, Ah, HD,
                                                            2 * HD, HF_TANH | HF_OUTH);

    // 8) logits
    logits_wmma<<<dim3(VV / 128, (BB * TD) / 128), 128, SMEM_LOGITS>>>(b_out, out);

    // 9) h_last tail
    copy_hlast<<<BB, HD>>>(out + LOGITS_ELEMS);
}